// round 10
// baseline (speedup 1.0000x reference)
#include <cuda_runtime.h>
#include <cuda_fp16.h>
#include <cstdint>

constexpr int SEQ   = 2048;
constexpr int CH    = 1024;
constexpr int NHEAD = 16;
constexpr int HDIM  = 64;

// ---------------------------------------------------------------------------
// Scratch
// ---------------------------------------------------------------------------
__device__ __half g_xh[SEQ * CH],  g_xl[SEQ * CH];           // x split, [w][c]
__device__ __half g_wth[4][CH * CH], g_wtl[4][CH * CH];      // W^T split, [n][k]
__device__ __half g_erth[SEQ * HDIM], g_ertl[SEQ * HDIM];    // er^T split, [i][d]
__device__ float  g_q0[SEQ * CH], g_k0[SEQ * CH], g_v0[SEQ * CH];
__device__ __half g_qch[SEQ * CH], g_qcl[SEQ * CH];          // conv(q) split, [w][c]
__device__ __half g_kch[SEQ * CH], g_kcl[SEQ * CH];
__device__ float  g_vc[SEQ * CH];                            // conv(v) fp32
__device__ __half g_vth[CH * SEQ], g_vtl[CH * SEQ];          // conv(v)^T split, [c][w]
__device__ __half g_ath[SEQ * CH], g_atl[SEQ * CH];          // attn split, [w][c]

// ---------------------------------------------------------------------------
// Helpers
// ---------------------------------------------------------------------------
__device__ __forceinline__ uint32_t smem_u32(const void* p) {
    uint32_t a;
    asm("{ .reg .u64 t; cvta.to.shared.u64 t, %1; cvt.u32.u64 %0, t; }" : "=r"(a) : "l"(p));
    return a;
}
__device__ __forceinline__ uint32_t h2u(__half2 v) {
    union { __half2 h; uint32_t u; } c;
    c.h = v;
    return c.u;
}
__device__ __forceinline__ void split_h(float x, __half& h, __half& l) {
    h = __float2half_rn(x);
    l = __float2half_rn(x - __half2float(h));
}
__device__ __forceinline__ void mma_f16(float* c, const uint32_t* a, const uint32_t* b) {
    asm volatile(
        "mma.sync.aligned.m16n8k16.row.col.f32.f16.f16.f32 "
        "{%0,%1,%2,%3},{%4,%5,%6,%7},{%8,%9},{%0,%1,%2,%3};"
        : "+f"(c[0]), "+f"(c[1]), "+f"(c[2]), "+f"(c[3])
        : "r"(a[0]), "r"(a[1]), "r"(a[2]), "r"(a[3]), "r"(b[0]), "r"(b[1]));
}
__device__ __forceinline__ void ldsm_x4(uint32_t* r, uint32_t addr) {
    asm volatile("ldmatrix.sync.aligned.m8n8.x4.shared.b16 {%0,%1,%2,%3}, [%4];"
        : "=r"(r[0]), "=r"(r[1]), "=r"(r[2]), "=r"(r[3]) : "r"(addr));
}
__device__ __forceinline__ void ldsm_x2(uint32_t* r, uint32_t addr) {
    asm volatile("ldmatrix.sync.aligned.m8n8.x2.shared.b16 {%0,%1}, [%2];"
        : "=r"(r[0]), "=r"(r[1]) : "r"(addr));
}
__device__ __forceinline__ void cpa16(uint32_t s, const void* g) {
    asm volatile("cp.async.ca.shared.global [%0], [%1], 16;" :: "r"(s), "l"(g));
}
#define CP_COMMIT() asm volatile("cp.async.commit_group;" ::: "memory")
#define CP_WAIT0()  asm volatile("cp.async.wait_group 0;" ::: "memory")
#define CP_WAIT1()  asm volatile("cp.async.wait_group 1;" ::: "memory")
#define CP_WAIT2()  asm volatile("cp.async.wait_group 2;" ::: "memory")

struct KtH { const __half* ah; const __half* al; const __half* bh; const __half* bl;
             int lda; int ldb; };

// ---------------------------------------------------------------------------
// 3-stage cp.async pipelined FP16x3 GEMM body (unchanged from R6)
// ---------------------------------------------------------------------------
template<int BM, int BN, int WM, int WN, bool OSPL, typename F>
__device__ __forceinline__ void gemm_pipe(
    F&& ktf, int KT, float* C, __half* Ch, __half* Cl, int ldc, float alpha, char* sm_)
{
    constexpr int WARPS_M = BM / WM, WARPS_N = BN / WN;
    static_assert(WARPS_M * WARPS_N == 8, "");
    constexpr int MT = WM / 16, NT = WN / 8;
    constexpr int ABYT = BM * 48, BBYT = BN * 48;
    constexpr int STB  = 2 * ABYT + 2 * BBYT;
    constexpr int NSTG = 3;

    const uint32_t sb = smem_u32(sm_);
    const int tid = threadIdx.x, wid = tid >> 5, lane = tid & 31;
    const int gid = lane >> 2, tig = lane & 3;
    const int wm0 = (wid % WARPS_M) * WM, wn0 = (wid / WARPS_M) * WN;

    auto issue = [&](int s, int t) {
        KtH p = ktf(t);
        uint32_t st = sb + s * STB;
        #pragma unroll
        for (int i = 0; i < BM * 2 / 256; i++) {
            int id = tid + i * 256, row = id >> 1, c16 = id & 1;
            uint32_t sa = st + row * 48 + c16 * 16;
            cpa16(sa,        p.ah + (long long)row * p.lda + c16 * 8);
            cpa16(sa + ABYT, p.al + (long long)row * p.lda + c16 * 8);
        }
        #pragma unroll
        for (int i = 0; i < (BN * 2 + 255) / 256; i++) {
            int id = tid + i * 256;
            if (id < BN * 2) {
                int row = id >> 1, c16 = id & 1;
                uint32_t sa = st + 2 * ABYT + row * 48 + c16 * 16;
                cpa16(sa,        p.bh + (long long)row * p.ldb + c16 * 8);
                cpa16(sa + BBYT, p.bl + (long long)row * p.ldb + c16 * 8);
            }
        }
    };

    float acc[MT][NT][4] = {};

    #pragma unroll
    for (int s = 0; s < NSTG; s++) {
        if (s < KT) issue(s, s);
        CP_COMMIT();
    }

    for (int t = 0; t < KT; t++) {
        int s = t % NSTG;
        CP_WAIT2();
        __syncthreads();

        uint32_t base = sb + s * STB;
        uint32_t ah[MT][4], al[MT][4], bh[NT][2], bl[NT][2];
        #pragma unroll
        for (int mt = 0; mt < MT; mt++) {
            uint32_t a0 = base + (wm0 + mt * 16 + (lane & 15)) * 48 + (lane >> 4) * 16;
            ldsm_x4(ah[mt], a0);
            ldsm_x4(al[mt], a0 + ABYT);
        }
        #pragma unroll
        for (int nt = 0; nt < NT; nt++) {
            uint32_t b0 = base + 2 * ABYT + (wn0 + nt * 8 + (lane & 7)) * 48
                        + ((lane >> 3) & 1) * 16;
            ldsm_x2(bh[nt], b0);
            ldsm_x2(bl[nt], b0 + BBYT);
        }
        #pragma unroll
        for (int mt = 0; mt < MT; mt++)
            #pragma unroll
            for (int nt = 0; nt < NT; nt++) {
                mma_f16(acc[mt][nt], ah[mt], bh[nt]);
                mma_f16(acc[mt][nt], ah[mt], bl[nt]);
                mma_f16(acc[mt][nt], al[mt], bh[nt]);
            }
        __syncthreads();
        if (t + NSTG < KT) issue(s, t + NSTG);
        CP_COMMIT();
    }

    #pragma unroll
    for (int mt = 0; mt < MT; mt++)
        #pragma unroll
        for (int nt = 0; nt < NT; nt++) {
            int r = wm0 + mt * 16 + gid;
            int c = wn0 + nt * 8 + 2 * tig;
            #pragma unroll
            for (int half_ = 0; half_ < 2; half_++) {
                int rr = r + half_ * 8;
                float v0 = alpha * acc[mt][nt][half_ * 2 + 0];
                float v1 = alpha * acc[mt][nt][half_ * 2 + 1];
                if (OSPL) {
                    __half h0, l0, h1, l1;
                    split_h(v0, h0, l0); split_h(v1, h1, l1);
                    *(__half2*)(Ch + (long long)rr * ldc + c) = __halves2half2(h0, h1);
                    *(__half2*)(Cl + (long long)rr * ldc + c) = __halves2half2(l0, l1);
                } else {
                    *(float2*)(C + (long long)rr * ldc + c) = make_float2(v0, v1);
                }
            }
        }
}

__global__ __launch_bounds__(256, 2) void qkv_pipe()
{
    extern __shared__ char smem[];
    const int z = blockIdx.z;
    const int m0 = blockIdx.y * 128, n0 = blockIdx.x * 128;
    float* O = ((z == 0) ? g_q0 : (z == 1) ? g_k0 : g_v0) + (long long)m0 * CH + n0;
    const __half* Ah = g_xh + (long long)m0 * CH;
    const __half* Al = g_xl + (long long)m0 * CH;
    const __half* Bh = g_wth[z] + (long long)n0 * CH;
    const __half* Bl = g_wtl[z] + (long long)n0 * CH;
    auto ktf = [&](int t) -> KtH {
        return { Ah + t * 16, Al + t * 16, Bh + t * 16, Bl + t * 16, CH, CH };
    };
    gemm_pipe<128, 128, 64, 32, false>(ktf, CH / 16, O, nullptr, nullptr, CH, 1.f, smem);
}

__global__ __launch_bounds__(256, 2) void wo_pipe(float* __restrict__ out)
{
    extern __shared__ char smem[];
    const int m0 = blockIdx.y * 128, n0 = blockIdx.x * 128;
    const __half* Ah = g_ath + (long long)m0 * CH;
    const __half* Al = g_atl + (long long)m0 * CH;
    const __half* Bh = g_wth[3] + (long long)n0 * CH;
    const __half* Bl = g_wtl[3] + (long long)n0 * CH;
    float* O = out + (long long)m0 * CH + n0;
    auto ktf = [&](int t) -> KtH {
        return { Ah + t * 16, Al + t * 16, Bh + t * 16, Bl + t * 16, CH, CH };
    };
    gemm_pipe<128, 128, 64, 32, false>(ktf, CH / 16, O, nullptr, nullptr, CH, 1.f, smem);
}

// ---------------------------------------------------------------------------
// Fused flash attention: scores(+rel-pos) + online softmax + P@V
// Grid: (SEQ/128, NHEAD). 8 warps x 16 rows. j-blocks of 64.
// Virtual K=128: kt 0-3 = Q_i . K_j (d), kt 4-7 = ErT_i . Q_j (d).
// ---------------------------------------------------------------------------
constexpr int FA_STAGE = 55296;
constexpr int OFF_KH = 0,     OFF_KL = 9216,  OFF_QJH = 18432;
constexpr int OFF_QJL = 27648, OFF_VTH = 36864, OFF_VTL = 46080;

__global__ __launch_bounds__(256, 1) void flash_attn()
{
    extern __shared__ char smem[];
    const uint32_t sb = smem_u32(smem);
    const int tid = threadIdx.x, wid = tid >> 5, lane = tid & 31;
    const int gid = lane >> 2, tig = lane & 3;
    const int i0 = blockIdx.x * 128, hd = blockIdx.y, cb = hd * HDIM;
    const int r0w = wid * 16;

    // ---- initial: load Qi (h,l) and ErT (h,l) tiles (128 rows x 8 chunks
    //      = 1024 chunks per array), then extract A fragments ----
    #pragma unroll
    for (int i = 0; i < 4; i++) {
        int id = tid + i * 256;
        int row = id >> 3, ch = id & 7;
        cpa16(sb + 0     + row * 144 + ch * 16, g_qch + (long long)(i0 + row) * CH + cb + ch * 8);
        cpa16(sb + 18432 + row * 144 + ch * 16, g_qcl + (long long)(i0 + row) * CH + cb + ch * 8);
        cpa16(sb + 36864 + row * 144 + ch * 16, g_erth + (long long)(i0 + row) * HDIM + ch * 8);
        cpa16(sb + FA_STAGE + row * 144 + ch * 16, g_ertl + (long long)(i0 + row) * HDIM + ch * 8);
    }
    CP_COMMIT();
    CP_WAIT0();
    __syncthreads();

    uint32_t afh[8][4], afl[8][4];
    #pragma unroll
    for (int kt = 0; kt < 4; kt++) {
        uint32_t a = sb + (r0w + (lane & 15)) * 144 + kt * 32 + (lane >> 4) * 16;
        ldsm_x4(afh[kt], a);
        ldsm_x4(afl[kt], a + 18432);
        uint32_t e = sb + 36864 + (r0w + (lane & 15)) * 144 + kt * 32 + (lane >> 4) * 16;
        ldsm_x4(afh[4 + kt], e);
        ldsm_x4(afl[4 + kt], sb + FA_STAGE + (r0w + (lane & 15)) * 144 + kt * 32 + (lane >> 4) * 16);
    }
    __syncthreads();

    auto issue_j = [&](int jb, int s) {
        uint32_t st = sb + s * FA_STAGE;
        int j0 = jb * 64;
        #pragma unroll
        for (int i = 0; i < 2; i++) {
            int id = tid + i * 256;        // 512 chunks per array (64 rows x 8)
            int row = id >> 3, ch = id & 7;
            long long ro = (long long)(j0 + row) * CH + cb + ch * 8;
            cpa16(st + OFF_KH  + row * 144 + ch * 16, g_kch + ro);
            cpa16(st + OFF_KL  + row * 144 + ch * 16, g_kcl + ro);
            cpa16(st + OFF_QJH + row * 144 + ch * 16, g_qch + ro);
            cpa16(st + OFF_QJL + row * 144 + ch * 16, g_qcl + ro);
            long long vo = (long long)(hd * HDIM + row) * SEQ + j0 + ch * 8;
            cpa16(st + OFF_VTH + row * 144 + ch * 16, g_vth + vo);
            cpa16(st + OFF_VTL + row * 144 + ch * 16, g_vtl + vo);
        }
    };

    issue_j(0, 0); CP_COMMIT();
    issue_j(1, 1); CP_COMMIT();

    float of[8][4] = {};
    float m0 = -1e30f, m1 = -1e30f, sum0 = 0.f, sum1 = 0.f;
    const float sc = 0.03125f;   // 1/sqrt(1024)

    for (int t = 0; t < 32; t++) {
        CP_WAIT1();
        __syncthreads();
        const uint32_t st = sb + (t & 1) * FA_STAGE;

        // ---- S tile: 16 rows x 64 cols, virtual K = 128 ----
        float s_[8][4] = {};
        #pragma unroll
        for (int nt = 0; nt < 8; nt++) {
            #pragma unroll
            for (int ktp = 0; ktp < 4; ktp++) {
                uint32_t bbase = st + ((ktp < 2) ? OFF_KH : OFF_QJH)
                               + (nt * 8 + (lane & 7)) * 144 + (ktp & 1) * 64
                               + (lane >> 3) * 16;
                uint32_t bh[4], bl[4];
                ldsm_x4(bh, bbase);
                ldsm_x4(bl, bbase + 9216);
                int ka = 2 * ktp, kb = ka + 1;
                mma_f16(s_[nt], afh[ka], bh + 0);
                mma_f16(s_[nt], afh[ka], bl + 0);
                mma_f16(s_[nt], afl[ka], bh + 0);
                mma_f16(s_[nt], afh[kb], bh + 2);
                mma_f16(s_[nt], afh[kb], bl + 2);
                mma_f16(s_[nt], afl[kb], bh + 2);
            }
        }

        // ---- online softmax ----
        float rm0 = -1e30f, rm1 = -1e30f;
        #pragma unroll
        for (int nt = 0; nt < 8; nt++) {
            s_[nt][0] *= sc; s_[nt][1] *= sc; s_[nt][2] *= sc; s_[nt][3] *= sc;
            rm0 = fmaxf(rm0, fmaxf(s_[nt][0], s_[nt][1]));
            rm1 = fmaxf(rm1, fmaxf(s_[nt][2], s_[nt][3]));
        }
        rm0 = fmaxf(rm0, __shfl_xor_sync(~0u, rm0, 1));
        rm0 = fmaxf(rm0, __shfl_xor_sync(~0u, rm0, 2));
        rm1 = fmaxf(rm1, __shfl_xor_sync(~0u, rm1, 1));
        rm1 = fmaxf(rm1, __shfl_xor_sync(~0u, rm1, 2));
        float mn0 = fmaxf(m0, rm0), mn1 = fmaxf(m1, rm1);
        float f0 = __expf(m0 - mn0), f1 = __expf(m1 - mn1);
        m0 = mn0; m1 = mn1;
        #pragma unroll
        for (int nt = 0; nt < 8; nt++) {
            of[nt][0] *= f0; of[nt][1] *= f0;
            of[nt][2] *= f1; of[nt][3] *= f1;
        }

        uint32_t ph[4][4], pl[4][4];
        float rs0 = 0.f, rs1 = 0.f;
        #pragma unroll
        for (int nt = 0; nt < 8; nt++) {
            float p0 = __expf(s_[nt][0] - mn0), p1 = __expf(s_[nt][1] - mn0);
            float p2 = __expf(s_[nt][2] - mn1), p3 = __expf(s_[nt][3] - mn1);
            rs0 += p0 + p1; rs1 += p2 + p3;
            __half h0, l0, h1, l1, h2, l2, h3, l3;
            split_h(p0, h0, l0); split_h(p1, h1, l1);
            split_h(p2, h2, l2); split_h(p3, h3, l3);
            int kt = nt >> 1;
            if ((nt & 1) == 0) {
                ph[kt][0] = h2u(__halves2half2(h0, h1));
                ph[kt][1] = h2u(__halves2half2(h2, h3));
                pl[kt][0] = h2u(__halves2half2(l0, l1));
                pl[kt][1] = h2u(__halves2half2(l2, l3));
            } else {
                ph[kt][2] = h2u(__halves2half2(h0, h1));
                ph[kt][3] = h2u(__halves2half2(h2, h3));
                pl[kt][2] = h2u(__halves2half2(l0, l1));
                pl[kt][3] = h2u(__halves2half2(l2, l3));
            }
        }
        rs0 += __shfl_xor_sync(~0u, rs0, 1); rs0 += __shfl_xor_sync(~0u, rs0, 2);
        rs1 += __shfl_xor_sync(~0u, rs1, 1); rs1 += __shfl_xor_sync(~0u, rs1, 2);
        sum0 = sum0 * f0 + rs0;
        sum1 = sum1 * f1 + rs1;

        // ---- P @ V : O += P(16x64) * V(64x64) ----
        #pragma unroll
        for (int nt = 0; nt < 8; nt++) {
            #pragma unroll
            for (int ktp = 0; ktp < 2; ktp++) {
                uint32_t vb = st + OFF_VTH + (nt * 8 + (lane & 7)) * 144 + ktp * 64
                            + (lane >> 3) * 16;
                uint32_t bvh[4], bvl[4];
                ldsm_x4(bvh, vb);
                ldsm_x4(bvl, vb + 9216);
                int ka = 2 * ktp, kb = ka + 1;
                mma_f16(of[nt], ph[ka], bvh + 0);
                mma_f16(of[nt], ph[ka], bvl + 0);
                mma_f16(of[nt], pl[ka], bvh + 0);
                mma_f16(of[nt], ph[kb], bvh + 2);
                mma_f16(of[nt], ph[kb], bvl + 2);
                mma_f16(of[nt], pl[kb], bvh + 2);
            }
        }

        __syncthreads();
        if (t + 2 < 32) issue_j(t + 2, t & 1);
        CP_COMMIT();
    }

    // ---- finalize ----
    float inv0 = 1.f / sum0, inv1 = 1.f / sum1;
    int row0 = i0 + r0w + gid;
    #pragma unroll
    for (int nt = 0; nt < 8; nt++) {
        int col = cb + nt * 8 + 2 * tig;
        float v0 = of[nt][0] * inv0, v1 = of[nt][1] * inv0;
        float v2 = of[nt][2] * inv1, v3 = of[nt][3] * inv1;
        __half h0, l0, h1, l1, h2, l2, h3, l3;
        split_h(v0, h0, l0); split_h(v1, h1, l1);
        split_h(v2, h2, l2); split_h(v3, h3, l3);
        *(__half2*)(g_ath + (long long)row0 * CH + col) = __halves2half2(h0, h1);
        *(__half2*)(g_atl + (long long)row0 * CH + col) = __halves2half2(l0, l1);
        *(__half2*)(g_ath + (long long)(row0 + 8) * CH + col) = __halves2half2(h2, h3);
        *(__half2*)(g_atl + (long long)(row0 + 8) * CH + col) = __halves2half2(l2, l3);
    }
}

// ---------------------------------------------------------------------------
// Prep kernels
// ---------------------------------------------------------------------------
__global__ __launch_bounds__(256) void split_x(const float* __restrict__ x)
{
    int i = blockIdx.x * 256 + threadIdx.x;
    if (i >= SEQ * CH) return;
    __half h, l; split_h(x[i], h, l);
    g_xh[i] = h; g_xl[i] = l;
}

__global__ void transpose_split(const float* __restrict__ in,
                                __half* __restrict__ oh, __half* __restrict__ ol,
                                int R, int C)
{
    __shared__ float t[32][33];
    int c0 = blockIdx.x * 32, r0 = blockIdx.y * 32;
    int tx = threadIdx.x, ty = threadIdx.y;   // 32 x 8
    #pragma unroll
    for (int j = 0; j < 4; j++)
        t[ty + 8 * j][tx] = in[(long long)(r0 + ty + 8 * j) * C + c0 + tx];
    __syncthreads();
    #pragma unroll
    for (int j = 0; j < 4; j++) {
        float v = t[tx][ty + 8 * j];
        __half h, l; split_h(v, h, l);
        long long o = (long long)(c0 + ty + 8 * j) * R + r0 + tx;
        oh[o] = h; ol[o] = l;
    }
}

__global__ __launch_bounds__(256) void dwconv3(const float* __restrict__ cw)
{
    const int z = blockIdx.y;
    const float* X = (z == 0) ? g_q0 : (z == 1) ? g_k0 : g_v0;
    int idx = blockIdx.x * 256 + threadIdx.x;
    if (idx >= SEQ * CH) return;
    int c = idx & (CH - 1);
    int w = idx >> 10;
    float w0 = cw[c * 3 + 0], w1 = cw[c * 3 + 1], w2 = cw[c * 3 + 2];
    float acc = X[idx] * w1;
    if (w > 0)       acc += X[idx - CH] * w0;
    if (w < SEQ - 1) acc += X[idx + CH] * w2;
    if (z == 2) { g_vc[idx] = acc; return; }
    __half h, l; split_h(acc, h, l);
    if (z == 0) { g_qch[idx] = h; g_qcl[idx] = l; }
    else        { g_kch[idx] = h; g_kcl[idx] = l; }
}

// ---------------------------------------------------------------------------
// Launch
// ---------------------------------------------------------------------------
extern "C" void kernel_launch(void* const* d_in, const int* in_sizes, int n_in,
                              void* d_out, int out_size)
{
    const float* x  = (const float*)d_in[0];
    const float* wq = (const float*)d_in[1];
    const float* wk = (const float*)d_in[2];
    const float* wv = (const float*)d_in[3];
    const float* wo = (const float*)d_in[4];
    const float* cw = (const float*)d_in[5];
    const float* er = (const float*)d_in[6];
    float* out = (float*)d_out;

    __half *wth, *wtl, *erth, *ertl, *vth, *vtl;
    float* vc;
    cudaGetSymbolAddress((void**)&wth,  g_wth);
    cudaGetSymbolAddress((void**)&wtl,  g_wtl);
    cudaGetSymbolAddress((void**)&erth, g_erth);
    cudaGetSymbolAddress((void**)&ertl, g_ertl);
    cudaGetSymbolAddress((void**)&vth,  g_vth);
    cudaGetSymbolAddress((void**)&vtl,  g_vtl);
    cudaGetSymbolAddress((void**)&vc,   g_vc);

    const int SM128 = (2 * 128 * 48 + 2 * 128 * 48) * 3;   // 73,728
    const int SMFA  = 2 * FA_STAGE;                        // 110,592
    cudaFuncSetAttribute(qkv_pipe,   cudaFuncAttributeMaxDynamicSharedMemorySize, SM128);
    cudaFuncSetAttribute(wo_pipe,    cudaFuncAttributeMaxDynamicSharedMemorySize, SM128);
    cudaFuncSetAttribute(flash_attn, cudaFuncAttributeMaxDynamicSharedMemorySize, SMFA);

    dim3 blk(256);
    dim3 tblk(32, 8);

    split_x<<<SEQ * CH / 256, blk>>>(x);
    const float* ws[4] = {wq, wk, wv, wo};
    for (int z = 0; z < 4; z++)
        transpose_split<<<dim3(32, 32), tblk>>>(ws[z], wth + (long long)z * CH * CH,
                                                wtl + (long long)z * CH * CH, CH, CH);
    transpose_split<<<dim3(64, 2), tblk>>>(er, erth, ertl, HDIM, SEQ);

    qkv_pipe<<<dim3(CH / 128, SEQ / 128, 3), blk, SM128>>>();
    dwconv3<<<dim3(SEQ * CH / 256, 3), blk>>>(cw);
    transpose_split<<<dim3(32, 64), tblk>>>(vc, vth, vtl, SEQ, CH);

    flash_attn<<<dim3(SEQ / 128, NHEAD), blk, SMFA>>>();

    wo_pipe<<<dim3(CH / 128, SEQ / 128, 1), blk, SM128>>>(out);
}

// round 11
// speedup vs baseline: 1.2679x; 1.2679x over previous
#include <cuda_runtime.h>
#include <cuda_fp16.h>
#include <cstdint>

constexpr int SEQ   = 2048;
constexpr int CH    = 1024;
constexpr int NHEAD = 16;
constexpr int HDIM  = 64;

// ---------------------------------------------------------------------------
// Scratch
// ---------------------------------------------------------------------------
__device__ __half g_xh[SEQ * CH],  g_xl[SEQ * CH];           // x split, [w][c]
__device__ __half g_wth[4][CH * CH], g_wtl[4][CH * CH];      // W^T split, [n][k]
__device__ __half g_erth[SEQ * HDIM], g_ertl[SEQ * HDIM];    // er^T split, [i][d]
__device__ float  g_q0[SEQ * CH], g_k0[SEQ * CH], g_v0[SEQ * CH];
__device__ __half g_qch[SEQ * CH], g_qcl[SEQ * CH];          // conv(q) split, [w][c]
__device__ __half g_kch[SEQ * CH], g_kcl[SEQ * CH];
__device__ float  g_vc[SEQ * CH];                            // conv(v) fp32
__device__ __half g_vth[CH * SEQ], g_vtl[CH * SEQ];          // conv(v)^T split, [c][w]
__device__ __half g_Sh[(long long)NHEAD * SEQ * SEQ];        // half scores -> probs (in-place)
__device__ __half g_ath[SEQ * CH], g_atl[SEQ * CH];          // attn split, [w][c]

// ---------------------------------------------------------------------------
// Helpers
// ---------------------------------------------------------------------------
__device__ __forceinline__ uint32_t smem_u32(const void* p) {
    uint32_t a;
    asm("{ .reg .u64 t; cvta.to.shared.u64 t, %1; cvt.u32.u64 %0, t; }" : "=r"(a) : "l"(p));
    return a;
}
__device__ __forceinline__ void split_h(float x, __half& h, __half& l) {
    h = __float2half_rn(x);
    l = __float2half_rn(x - __half2float(h));
}
__device__ __forceinline__ void mma_f16(float* c, const uint32_t* a, const uint32_t* b) {
    asm volatile(
        "mma.sync.aligned.m16n8k16.row.col.f32.f16.f16.f32 "
        "{%0,%1,%2,%3},{%4,%5,%6,%7},{%8,%9},{%0,%1,%2,%3};"
        : "+f"(c[0]), "+f"(c[1]), "+f"(c[2]), "+f"(c[3])
        : "r"(a[0]), "r"(a[1]), "r"(a[2]), "r"(a[3]), "r"(b[0]), "r"(b[1]));
}
__device__ __forceinline__ void ldsm_x4(uint32_t* r, uint32_t addr) {
    asm volatile("ldmatrix.sync.aligned.m8n8.x4.shared.b16 {%0,%1,%2,%3}, [%4];"
        : "=r"(r[0]), "=r"(r[1]), "=r"(r[2]), "=r"(r[3]) : "r"(addr));
}
__device__ __forceinline__ void ldsm_x2(uint32_t* r, uint32_t addr) {
    asm volatile("ldmatrix.sync.aligned.m8n8.x2.shared.b16 {%0,%1}, [%2];"
        : "=r"(r[0]), "=r"(r[1]) : "r"(addr));
}
__device__ __forceinline__ void cpa16(uint32_t s, const void* g) {
    asm volatile("cp.async.ca.shared.global [%0], [%1], 16;" :: "r"(s), "l"(g));
}
#define CP_COMMIT() asm volatile("cp.async.commit_group;" ::: "memory")
#define CP_WAIT2()  asm volatile("cp.async.wait_group 2;" ::: "memory")

struct KtH { const __half* ah; const __half* al; const __half* bh; const __half* bl;
             int lda; int ldb; };

// ---------------------------------------------------------------------------
// 3-stage cp.async pipelined FP16 GEMM body (m16n8k16), ldmatrix fragments.
// ASPL: A is hi/lo split (x3 MMAs) or single (x2 MMAs).
// OMODE: 0 = fp32 C, 1 = split half Ch/Cl, 2 = half Ch only.
// A smem: [m][k] rows of 16 halfs, stride 48 B. B smem: [n][k] same.
// ---------------------------------------------------------------------------
template<int BM, int BN, int WM, int WN, bool ASPL, int OMODE, typename F>
__device__ __forceinline__ void gemm_pipe(
    F&& ktf, int KT, float* C, __half* Ch, __half* Cl, int ldc, float alpha, char* sm_)
{
    constexpr int WARPS_M = BM / WM, WARPS_N = BN / WN;
    static_assert(WARPS_M * WARPS_N == 8, "");
    constexpr int MT = WM / 16, NT = WN / 8;
    constexpr int ABYT = BM * 48, BBYT = BN * 48;
    constexpr int NAARR = ASPL ? 2 : 1;
    constexpr int STB  = NAARR * ABYT + 2 * BBYT;
    constexpr int NSTG = 3;

    const uint32_t sb = smem_u32(sm_);
    const int tid = threadIdx.x, wid = tid >> 5, lane = tid & 31;
    const int gid = lane >> 2, tig = lane & 3;
    const int wm0 = (wid % WARPS_M) * WM, wn0 = (wid / WARPS_M) * WN;

    auto issue = [&](int s, int t) {
        KtH p = ktf(t);
        uint32_t st = sb + s * STB;
        #pragma unroll
        for (int i = 0; i < BM * 2 / 256; i++) {
            int id = tid + i * 256, row = id >> 1, c16 = id & 1;
            uint32_t sa = st + row * 48 + c16 * 16;
            cpa16(sa, p.ah + (long long)row * p.lda + c16 * 8);
            if (ASPL) cpa16(sa + ABYT, p.al + (long long)row * p.lda + c16 * 8);
        }
        #pragma unroll
        for (int i = 0; i < (BN * 2 + 255) / 256; i++) {
            int id = tid + i * 256;
            if (id < BN * 2) {
                int row = id >> 1, c16 = id & 1;
                uint32_t sa = st + NAARR * ABYT + row * 48 + c16 * 16;
                cpa16(sa,        p.bh + (long long)row * p.ldb + c16 * 8);
                cpa16(sa + BBYT, p.bl + (long long)row * p.ldb + c16 * 8);
            }
        }
    };

    float acc[MT][NT][4] = {};

    #pragma unroll
    for (int s = 0; s < NSTG; s++) {
        if (s < KT) issue(s, s);
        CP_COMMIT();
    }

    for (int t = 0; t < KT; t++) {
        int s = t % NSTG;
        CP_WAIT2();
        __syncthreads();

        uint32_t base = sb + s * STB;
        uint32_t ah[MT][4], al[MT][4], bh[NT][2], bl[NT][2];
        #pragma unroll
        for (int mt = 0; mt < MT; mt++) {
            uint32_t a0 = base + (wm0 + mt * 16 + (lane & 15)) * 48 + (lane >> 4) * 16;
            ldsm_x4(ah[mt], a0);
            if (ASPL) ldsm_x4(al[mt], a0 + ABYT);
        }
        #pragma unroll
        for (int nt = 0; nt < NT; nt++) {
            uint32_t b0 = base + NAARR * ABYT + (wn0 + nt * 8 + (lane & 7)) * 48
                        + ((lane >> 3) & 1) * 16;
            ldsm_x2(bh[nt], b0);
            ldsm_x2(bl[nt], b0 + BBYT);
        }
        #pragma unroll
        for (int mt = 0; mt < MT; mt++)
            #pragma unroll
            for (int nt = 0; nt < NT; nt++) {
                mma_f16(acc[mt][nt], ah[mt], bh[nt]);
                mma_f16(acc[mt][nt], ah[mt], bl[nt]);
                if (ASPL) mma_f16(acc[mt][nt], al[mt], bh[nt]);
            }
        __syncthreads();
        if (t + NSTG < KT) issue(s, t + NSTG);
        CP_COMMIT();
    }

    #pragma unroll
    for (int mt = 0; mt < MT; mt++)
        #pragma unroll
        for (int nt = 0; nt < NT; nt++) {
            int r = wm0 + mt * 16 + gid;
            int c = wn0 + nt * 8 + 2 * tig;
            #pragma unroll
            for (int half_ = 0; half_ < 2; half_++) {
                int rr = r + half_ * 8;
                float v0 = alpha * acc[mt][nt][half_ * 2 + 0];
                float v1 = alpha * acc[mt][nt][half_ * 2 + 1];
                if (OMODE == 1) {
                    __half h0, l0, h1, l1;
                    split_h(v0, h0, l0); split_h(v1, h1, l1);
                    *(__half2*)(Ch + (long long)rr * ldc + c) = __halves2half2(h0, h1);
                    *(__half2*)(Cl + (long long)rr * ldc + c) = __halves2half2(l0, l1);
                } else if (OMODE == 2) {
                    *(__half2*)(Ch + (long long)rr * ldc + c) = __floats2half2_rn(v0, v1);
                } else {
                    *(float2*)(C + (long long)rr * ldc + c) = make_float2(v0, v1);
                }
            }
        }
}

// ---------------------------------------------------------------------------
// GEMM kernels
// ---------------------------------------------------------------------------
__global__ __launch_bounds__(256, 2) void qkv_pipe()
{
    extern __shared__ char smem[];
    const int z = blockIdx.z;
    const int m0 = blockIdx.y * 128, n0 = blockIdx.x * 128;
    float* O = ((z == 0) ? g_q0 : (z == 1) ? g_k0 : g_v0) + (long long)m0 * CH + n0;
    const __half* Ah = g_xh + (long long)m0 * CH;
    const __half* Al = g_xl + (long long)m0 * CH;
    const __half* Bh = g_wth[z] + (long long)n0 * CH;
    const __half* Bl = g_wtl[z] + (long long)n0 * CH;
    auto ktf = [&](int t) -> KtH {
        return { Ah + t * 16, Al + t * 16, Bh + t * 16, Bl + t * 16, CH, CH };
    };
    gemm_pipe<128, 128, 64, 32, true, 0>(ktf, CH / 16, O, nullptr, nullptr, CH, 1.f, smem);
}

__global__ __launch_bounds__(256, 2) void wo_pipe(float* __restrict__ out)
{
    extern __shared__ char smem[];
    const int m0 = blockIdx.y * 128, n0 = blockIdx.x * 128;
    const __half* Ah = g_ath + (long long)m0 * CH;
    const __half* Al = g_atl + (long long)m0 * CH;
    const __half* Bh = g_wth[3] + (long long)n0 * CH;
    const __half* Bl = g_wtl[3] + (long long)n0 * CH;
    float* O = out + (long long)m0 * CH + n0;
    auto ktf = [&](int t) -> KtH {
        return { Ah + t * 16, Al + t * 16, Bh + t * 16, Bl + t * 16, CH, CH };
    };
    gemm_pipe<128, 128, 64, 32, true, 0>(ktf, CH / 16, O, nullptr, nullptr, CH, 1.f, smem);
}

// Score: S[h,i,j] = ( q_i.k_j + erT_i.q_j ) / 32 — virtual K = 128 (8 k-tiles).
// Output: HALF scores straight into g_Sh.
__global__ __launch_bounds__(256, 2) void score_pipe()
{
    extern __shared__ char smem[];
    const int h = blockIdx.z, cb = h * HDIM;
    const int i0 = blockIdx.y * 128, j0 = blockIdx.x * 128;
    __half* O = g_Sh + ((long long)h * SEQ + i0) * SEQ + j0;
    auto ktf = [&](int t) -> KtH {
        if (t < 4)
            return { g_qch + (long long)i0 * CH + cb + t * 16,
                     g_qcl + (long long)i0 * CH + cb + t * 16,
                     g_kch + (long long)j0 * CH + cb + t * 16,
                     g_kcl + (long long)j0 * CH + cb + t * 16, CH, CH };
        int d0 = (t - 4) * 16;
        return { g_erth + (long long)i0 * HDIM + d0,
                 g_ertl + (long long)i0 * HDIM + d0,
                 g_qch + (long long)j0 * CH + cb + d0,
                 g_qcl + (long long)j0 * CH + cb + d0, HDIM, CH };
    };
    gemm_pipe<128, 128, 64, 32, true, 2>(ktf, 8, nullptr, O, nullptr, SEQ, 0.03125f, smem);
}

// A @ V per head: M=2048, N=64, K=2048. A = probs (hi only), B = V^T split.
// Output split half for the wo projection.
__global__ __launch_bounds__(256, 2) void av_pipe()
{
    extern __shared__ char smem[];
    const int h = blockIdx.z;
    const int m0 = blockIdx.y * 128;
    const __half* Ah = g_Sh + ((long long)h * SEQ + m0) * SEQ;
    const __half* Bh = g_vth + (long long)(h * HDIM) * SEQ;
    const __half* Bl = g_vtl + (long long)(h * HDIM) * SEQ;
    __half* Oh = g_ath + (long long)m0 * CH + h * HDIM;
    __half* Ol = g_atl + (long long)m0 * CH + h * HDIM;
    auto ktf = [&](int t) -> KtH {
        return { Ah + t * 16, Ah + t * 16, Bh + t * 16, Bl + t * 16, SEQ, SEQ };
    };
    gemm_pipe<128, 64, 32, 32, false, 1>(ktf, SEQ / 16, nullptr, Oh, Ol, CH, 1.f, smem);
}

// ---------------------------------------------------------------------------
// Prep kernels
// ---------------------------------------------------------------------------
__global__ __launch_bounds__(256) void split_x(const float* __restrict__ x)
{
    int i = blockIdx.x * 256 + threadIdx.x;
    if (i >= SEQ * CH) return;
    __half h, l; split_h(x[i], h, l);
    g_xh[i] = h; g_xl[i] = l;
}

__global__ void transpose_split(const float* __restrict__ in,
                                __half* __restrict__ oh, __half* __restrict__ ol,
                                int R, int C)
{
    __shared__ float t[32][33];
    int c0 = blockIdx.x * 32, r0 = blockIdx.y * 32;
    int tx = threadIdx.x, ty = threadIdx.y;   // 32 x 8
    #pragma unroll
    for (int j = 0; j < 4; j++)
        t[ty + 8 * j][tx] = in[(long long)(r0 + ty + 8 * j) * C + c0 + tx];
    __syncthreads();
    #pragma unroll
    for (int j = 0; j < 4; j++) {
        float v = t[tx][ty + 8 * j];
        __half h, l; split_h(v, h, l);
        long long o = (long long)(c0 + ty + 8 * j) * R + r0 + tx;
        oh[o] = h; ol[o] = l;
    }
}

__global__ __launch_bounds__(256) void dwconv3(const float* __restrict__ cw)
{
    const int z = blockIdx.y;
    const float* X = (z == 0) ? g_q0 : (z == 1) ? g_k0 : g_v0;
    int idx = blockIdx.x * 256 + threadIdx.x;
    if (idx >= SEQ * CH) return;
    int c = idx & (CH - 1);
    int w = idx >> 10;
    float w0 = cw[c * 3 + 0], w1 = cw[c * 3 + 1], w2 = cw[c * 3 + 2];
    float acc = X[idx] * w1;
    if (w > 0)       acc += X[idx - CH] * w0;
    if (w < SEQ - 1) acc += X[idx + CH] * w2;
    if (z == 2) { g_vc[idx] = acc; return; }
    __half h, l; split_h(acc, h, l);
    if (z == 0) { g_qch[idx] = h; g_qcl[idx] = l; }
    else        { g_kch[idx] = h; g_kcl[idx] = l; }
}

// ---------------------------------------------------------------------------
// Softmax over half rows of g_Sh, in place: scores (half) -> probs (half).
// One row = 2048 halfs; 256 threads x 8 (one uint4 each).
// ---------------------------------------------------------------------------
__global__ __launch_bounds__(256) void softmax_rows()
{
    long long ro = ((long long)blockIdx.y * SEQ + blockIdx.x) * SEQ;
    uint4* row4 = (uint4*)(g_Sh + ro);
    const int tid = threadIdx.x;
    __shared__ float red[8];

    uint4 raw = row4[tid];
    __half2 hp[4] = { *(__half2*)&raw.x, *(__half2*)&raw.y,
                      *(__half2*)&raw.z, *(__half2*)&raw.w };
    float v[8];
    #pragma unroll
    for (int i = 0; i < 4; i++) {
        float2 f = __half22float2(hp[i]);
        v[2 * i] = f.x; v[2 * i + 1] = f.y;
    }

    float m = v[0];
    #pragma unroll
    for (int i = 1; i < 8; i++) m = fmaxf(m, v[i]);
    #pragma unroll
    for (int s = 16; s > 0; s >>= 1) m = fmaxf(m, __shfl_xor_sync(~0u, m, s));
    if ((tid & 31) == 0) red[tid >> 5] = m;
    __syncthreads();
    m = red[0];
    #pragma unroll
    for (int i = 1; i < 8; i++) m = fmaxf(m, red[i]);
    __syncthreads();

    float sum = 0.f;
    #pragma unroll
    for (int i = 0; i < 8; i++) { v[i] = __expf(v[i] - m); sum += v[i]; }
    #pragma unroll
    for (int s = 16; s > 0; s >>= 1) sum += __shfl_xor_sync(~0u, sum, s);
    if ((tid & 31) == 0) red[tid >> 5] = sum;
    __syncthreads();
    sum = 0.f;
    #pragma unroll
    for (int i = 0; i < 8; i++) sum += red[i];
    float inv = 1.0f / sum;

    uint4 outp;
    __half2* op = (__half2*)&outp;
    #pragma unroll
    for (int i = 0; i < 4; i++)
        op[i] = __floats2half2_rn(v[2 * i] * inv, v[2 * i + 1] * inv);
    row4[tid] = outp;
}

// ---------------------------------------------------------------------------
// Launch
// ---------------------------------------------------------------------------
extern "C" void kernel_launch(void* const* d_in, const int* in_sizes, int n_in,
                              void* d_out, int out_size)
{
    const float* x  = (const float*)d_in[0];
    const float* wq = (const float*)d_in[1];
    const float* wk = (const float*)d_in[2];
    const float* wv = (const float*)d_in[3];
    const float* wo = (const float*)d_in[4];
    const float* cw = (const float*)d_in[5];
    const float* er = (const float*)d_in[6];
    float* out = (float*)d_out;

    __half *wth, *wtl, *erth, *ertl, *vth, *vtl;
    float* vc;
    cudaGetSymbolAddress((void**)&wth,  g_wth);
    cudaGetSymbolAddress((void**)&wtl,  g_wtl);
    cudaGetSymbolAddress((void**)&erth, g_erth);
    cudaGetSymbolAddress((void**)&ertl, g_ertl);
    cudaGetSymbolAddress((void**)&vth,  g_vth);
    cudaGetSymbolAddress((void**)&vtl,  g_vtl);
    cudaGetSymbolAddress((void**)&vc,   g_vc);

    const int SM128 = (2 * 128 * 48 + 2 * 128 * 48) * 3;            // 73,728
    const int SMAV  = (1 * 128 * 48 + 2 * 64 * 48) * 3;             // 36,864
    cudaFuncSetAttribute(qkv_pipe,   cudaFuncAttributeMaxDynamicSharedMemorySize, SM128);
    cudaFuncSetAttribute(wo_pipe,    cudaFuncAttributeMaxDynamicSharedMemorySize, SM128);
    cudaFuncSetAttribute(score_pipe, cudaFuncAttributeMaxDynamicSharedMemorySize, SM128);
    cudaFuncSetAttribute(av_pipe,    cudaFuncAttributeMaxDynamicSharedMemorySize, SMAV);

    dim3 blk(256);
    dim3 tblk(32, 8);

    // prep: split x; transpose-split weights + er
    split_x<<<SEQ * CH / 256, blk>>>(x);
    const float* ws[4] = {wq, wk, wv, wo};
    for (int z = 0; z < 4; z++)
        transpose_split<<<dim3(32, 32), tblk>>>(ws[z], wth + (long long)z * CH * CH,
                                                wtl + (long long)z * CH * CH, CH, CH);
    transpose_split<<<dim3(64, 2), tblk>>>(er, erth, ertl, HDIM, SEQ);

    // q/k/v projections
    qkv_pipe<<<dim3(CH / 128, SEQ / 128, 3), blk, SM128>>>();

    // depthwise conv (reference applies q_conv to q, k AND v)
    dwconv3<<<dim3(SEQ * CH / 256, 3), blk>>>(cw);
    transpose_split<<<dim3(32, 64), tblk>>>(vc, vth, vtl, SEQ, CH);

    // scores (half out) + softmax (in place) + A@V
    score_pipe<<<dim3(SEQ / 128, SEQ / 128, NHEAD), blk, SM128>>>();
    softmax_rows<<<dim3(SEQ, NHEAD), blk>>>();
    av_pipe<<<dim3(1, SEQ / 128, NHEAD), blk, SMAV>>>();

    // output projection
    wo_pipe<<<dim3(CH / 128, SEQ / 128, 1), blk, SM128>>>(out);
}

// round 12
// speedup vs baseline: 1.3457x; 1.0613x over previous
#include <cuda_runtime.h>
#include <cuda_fp16.h>
#include <cstdint>

constexpr int SEQ   = 2048;
constexpr int CH    = 1024;
constexpr int NHEAD = 16;
constexpr int HDIM  = 64;

// ---------------------------------------------------------------------------
// Scratch
// ---------------------------------------------------------------------------
__device__ __half g_xh[SEQ * CH];                            // x -> half, [w][c]
__device__ __half g_wth[4][CH * CH], g_wtl[4][CH * CH];      // W^T split, [n][k]
__device__ __half g_erth[SEQ * HDIM], g_ertl[SEQ * HDIM];    // er^T split, [i][d]
__device__ float  g_q0[SEQ * CH], g_k0[SEQ * CH], g_v0[SEQ * CH];
__device__ __half g_qch[SEQ * CH], g_qcl[SEQ * CH];          // conv(q) split, [w][c]
__device__ __half g_kch[SEQ * CH], g_kcl[SEQ * CH];
__device__ float  g_vc[SEQ * CH];                            // conv(v) fp32
__device__ __half g_vth[CH * SEQ], g_vtl[CH * SEQ];          // conv(v)^T split, [c][w]
__device__ __half g_Sh[(long long)NHEAD * SEQ * SEQ];        // half scores -> probs (in-place)
__device__ __half g_ath[SEQ * CH];                           // attn half, [w][c]

// ---------------------------------------------------------------------------
// Helpers
// ---------------------------------------------------------------------------
__device__ __forceinline__ uint32_t smem_u32(const void* p) {
    uint32_t a;
    asm("{ .reg .u64 t; cvta.to.shared.u64 t, %1; cvt.u32.u64 %0, t; }" : "=r"(a) : "l"(p));
    return a;
}
__device__ __forceinline__ void split_h(float x, __half& h, __half& l) {
    h = __float2half_rn(x);
    l = __float2half_rn(x - __half2float(h));
}
__device__ __forceinline__ void mma_f16(float* c, const uint32_t* a, const uint32_t* b) {
    asm volatile(
        "mma.sync.aligned.m16n8k16.row.col.f32.f16.f16.f32 "
        "{%0,%1,%2,%3},{%4,%5,%6,%7},{%8,%9},{%0,%1,%2,%3};"
        : "+f"(c[0]), "+f"(c[1]), "+f"(c[2]), "+f"(c[3])
        : "r"(a[0]), "r"(a[1]), "r"(a[2]), "r"(a[3]), "r"(b[0]), "r"(b[1]));
}
__device__ __forceinline__ void ldsm_x4(uint32_t* r, uint32_t addr) {
    asm volatile("ldmatrix.sync.aligned.m8n8.x4.shared.b16 {%0,%1,%2,%3}, [%4];"
        : "=r"(r[0]), "=r"(r[1]), "=r"(r[2]), "=r"(r[3]) : "r"(addr));
}
__device__ __forceinline__ void ldsm_x2(uint32_t* r, uint32_t addr) {
    asm volatile("ldmatrix.sync.aligned.m8n8.x2.shared.b16 {%0,%1}, [%2];"
        : "=r"(r[0]), "=r"(r[1]) : "r"(addr));
}
__device__ __forceinline__ void cpa16(uint32_t s, const void* g) {
    asm volatile("cp.async.ca.shared.global [%0], [%1], 16;" :: "r"(s), "l"(g));
}
#define CP_COMMIT() asm volatile("cp.async.commit_group;" ::: "memory")
#define CP_WAIT2()  asm volatile("cp.async.wait_group 2;" ::: "memory")

struct KtH { const __half* ah; const __half* al; const __half* bh; const __half* bl;
             int lda; int ldb; };

// ---------------------------------------------------------------------------
// 3-stage cp.async pipelined FP16 GEMM body (m16n8k16), ldmatrix fragments.
// ASPL: A hi/lo split (x3 MMAs) or single A (x2 MMAs: ah*bh + ah*bl).
// OMODE: 0 = fp32 C, 1 = split half Ch/Cl, 2 = half Ch only.
// ---------------------------------------------------------------------------
template<int BM, int BN, int WM, int WN, bool ASPL, int OMODE, typename F>
__device__ __forceinline__ void gemm_pipe(
    F&& ktf, int KT, float* C, __half* Ch, __half* Cl, int ldc, float alpha, char* sm_)
{
    constexpr int WARPS_M = BM / WM, WARPS_N = BN / WN;
    static_assert(WARPS_M * WARPS_N == 8, "");
    constexpr int MT = WM / 16, NT = WN / 8;
    constexpr int ABYT = BM * 48, BBYT = BN * 48;
    constexpr int NAARR = ASPL ? 2 : 1;
    constexpr int STB  = NAARR * ABYT + 2 * BBYT;
    constexpr int NSTG = 3;

    const uint32_t sb = smem_u32(sm_);
    const int tid = threadIdx.x, wid = tid >> 5, lane = tid & 31;
    const int gid = lane >> 2, tig = lane & 3;
    const int wm0 = (wid % WARPS_M) * WM, wn0 = (wid / WARPS_M) * WN;

    auto issue = [&](int s, int t) {
        KtH p = ktf(t);
        uint32_t st = sb + s * STB;
        #pragma unroll
        for (int i = 0; i < BM * 2 / 256; i++) {
            int id = tid + i * 256, row = id >> 1, c16 = id & 1;
            uint32_t sa = st + row * 48 + c16 * 16;
            cpa16(sa, p.ah + (long long)row * p.lda + c16 * 8);
            if (ASPL) cpa16(sa + ABYT, p.al + (long long)row * p.lda + c16 * 8);
        }
        #pragma unroll
        for (int i = 0; i < (BN * 2 + 255) / 256; i++) {
            int id = tid + i * 256;
            if (id < BN * 2) {
                int row = id >> 1, c16 = id & 1;
                uint32_t sa = st + NAARR * ABYT + row * 48 + c16 * 16;
                cpa16(sa,        p.bh + (long long)row * p.ldb + c16 * 8);
                cpa16(sa + BBYT, p.bl + (long long)row * p.ldb + c16 * 8);
            }
        }
    };

    float acc[MT][NT][4] = {};

    #pragma unroll
    for (int s = 0; s < NSTG; s++) {
        if (s < KT) issue(s, s);
        CP_COMMIT();
    }

    for (int t = 0; t < KT; t++) {
        int s = t % NSTG;
        CP_WAIT2();
        __syncthreads();

        uint32_t base = sb + s * STB;
        uint32_t ah[MT][4], al[MT][4], bh[NT][2], bl[NT][2];
        #pragma unroll
        for (int mt = 0; mt < MT; mt++) {
            uint32_t a0 = base + (wm0 + mt * 16 + (lane & 15)) * 48 + (lane >> 4) * 16;
            ldsm_x4(ah[mt], a0);
            if (ASPL) ldsm_x4(al[mt], a0 + ABYT);
        }
        #pragma unroll
        for (int nt = 0; nt < NT; nt++) {
            uint32_t b0 = base + NAARR * ABYT + (wn0 + nt * 8 + (lane & 7)) * 48
                        + ((lane >> 3) & 1) * 16;
            ldsm_x2(bh[nt], b0);
            ldsm_x2(bl[nt], b0 + BBYT);
        }
        #pragma unroll
        for (int mt = 0; mt < MT; mt++)
            #pragma unroll
            for (int nt = 0; nt < NT; nt++) {
                mma_f16(acc[mt][nt], ah[mt], bh[nt]);
                mma_f16(acc[mt][nt], ah[mt], bl[nt]);
                if (ASPL) mma_f16(acc[mt][nt], al[mt], bh[nt]);
            }
        __syncthreads();
        if (t + NSTG < KT) issue(s, t + NSTG);
        CP_COMMIT();
    }

    #pragma unroll
    for (int mt = 0; mt < MT; mt++)
        #pragma unroll
        for (int nt = 0; nt < NT; nt++) {
            int r = wm0 + mt * 16 + gid;
            int c = wn0 + nt * 8 + 2 * tig;
            #pragma unroll
            for (int half_ = 0; half_ < 2; half_++) {
                int rr = r + half_ * 8;
                float v0 = alpha * acc[mt][nt][half_ * 2 + 0];
                float v1 = alpha * acc[mt][nt][half_ * 2 + 1];
                if (OMODE == 1) {
                    __half h0, l0, h1, l1;
                    split_h(v0, h0, l0); split_h(v1, h1, l1);
                    *(__half2*)(Ch + (long long)rr * ldc + c) = __halves2half2(h0, h1);
                    *(__half2*)(Cl + (long long)rr * ldc + c) = __halves2half2(l0, l1);
                } else if (OMODE == 2) {
                    *(__half2*)(Ch + (long long)rr * ldc + c) = __floats2half2_rn(v0, v1);
                } else {
                    *(float2*)(C + (long long)rr * ldc + c) = make_float2(v0, v1);
                }
            }
        }
}

// ---------------------------------------------------------------------------
// GEMM kernels
// ---------------------------------------------------------------------------
// q/k/v projections: A = x (half, single), B = W^T split  -> x2 MMAs
__global__ __launch_bounds__(256, 2) void qkv_pipe()
{
    extern __shared__ char smem[];
    const int z = blockIdx.z;
    const int m0 = blockIdx.y * 128, n0 = blockIdx.x * 128;
    float* O = ((z == 0) ? g_q0 : (z == 1) ? g_k0 : g_v0) + (long long)m0 * CH + n0;
    const __half* Ah = g_xh + (long long)m0 * CH;
    const __half* Bh = g_wth[z] + (long long)n0 * CH;
    const __half* Bl = g_wtl[z] + (long long)n0 * CH;
    auto ktf = [&](int t) -> KtH {
        return { Ah + t * 16, Ah + t * 16, Bh + t * 16, Bl + t * 16, CH, CH };
    };
    gemm_pipe<128, 128, 64, 32, false, 0>(ktf, CH / 16, O, nullptr, nullptr, CH, 1.f, smem);
}

// output projection: A = attn (half, single), B = wo^T split -> x2 MMAs
__global__ __launch_bounds__(256, 2) void wo_pipe(float* __restrict__ out)
{
    extern __shared__ char smem[];
    const int m0 = blockIdx.y * 128, n0 = blockIdx.x * 128;
    const __half* Ah = g_ath + (long long)m0 * CH;
    const __half* Bh = g_wth[3] + (long long)n0 * CH;
    const __half* Bl = g_wtl[3] + (long long)n0 * CH;
    float* O = out + (long long)m0 * CH + n0;
    auto ktf = [&](int t) -> KtH {
        return { Ah + t * 16, Ah + t * 16, Bh + t * 16, Bl + t * 16, CH, CH };
    };
    gemm_pipe<128, 128, 64, 32, false, 0>(ktf, CH / 16, O, nullptr, nullptr, CH, 1.f, smem);
}

// Score: S[h,i,j] = ( q_i.k_j + erT_i.q_j ) / 32 — virtual K = 128, x3, half out.
__global__ __launch_bounds__(256, 2) void score_pipe()
{
    extern __shared__ char smem[];
    const int h = blockIdx.z, cb = h * HDIM;
    const int i0 = blockIdx.y * 128, j0 = blockIdx.x * 128;
    __half* O = g_Sh + ((long long)h * SEQ + i0) * SEQ + j0;
    auto ktf = [&](int t) -> KtH {
        if (t < 4)
            return { g_qch + (long long)i0 * CH + cb + t * 16,
                     g_qcl + (long long)i0 * CH + cb + t * 16,
                     g_kch + (long long)j0 * CH + cb + t * 16,
                     g_kcl + (long long)j0 * CH + cb + t * 16, CH, CH };
        int d0 = (t - 4) * 16;
        return { g_erth + (long long)i0 * HDIM + d0,
                 g_ertl + (long long)i0 * HDIM + d0,
                 g_qch + (long long)j0 * CH + cb + d0,
                 g_qcl + (long long)j0 * CH + cb + d0, HDIM, CH };
    };
    gemm_pipe<128, 128, 64, 32, true, 2>(ktf, 8, nullptr, O, nullptr, SEQ, 0.03125f, smem);
}

// A @ V per head: A = probs (half single), B = V^T split. Half output (g_ath only).
__global__ __launch_bounds__(256, 2) void av_pipe()
{
    extern __shared__ char smem[];
    const int h = blockIdx.z;
    const int m0 = blockIdx.y * 128;
    const __half* Ah = g_Sh + ((long long)h * SEQ + m0) * SEQ;
    const __half* Bh = g_vth + (long long)(h * HDIM) * SEQ;
    const __half* Bl = g_vtl + (long long)(h * HDIM) * SEQ;
    __half* Oh = g_ath + (long long)m0 * CH + h * HDIM;
    auto ktf = [&](int t) -> KtH {
        return { Ah + t * 16, Ah + t * 16, Bh + t * 16, Bl + t * 16, SEQ, SEQ };
    };
    gemm_pipe<128, 64, 32, 32, false, 2>(ktf, SEQ / 16, nullptr, Oh, nullptr, CH, 1.f, smem);
}

// ---------------------------------------------------------------------------
// Prep kernels
// ---------------------------------------------------------------------------
__global__ __launch_bounds__(256) void split_x(const float* __restrict__ x)
{
    int i = blockIdx.x * 256 + threadIdx.x;
    if (i >= SEQ * CH) return;
    g_xh[i] = __float2half_rn(x[i]);
}

// in[R][C] fp32 -> out[C][R] split halves (tiled, coalesced both sides)
__device__ __forceinline__ void tsplit_body(
    const float* __restrict__ in, __half* __restrict__ oh, __half* __restrict__ ol,
    int R, int C)
{
    __shared__ float t[32][33];
    int c0 = blockIdx.x * 32, r0 = blockIdx.y * 32;
    int tx = threadIdx.x, ty = threadIdx.y;   // 32 x 8
    #pragma unroll
    for (int j = 0; j < 4; j++)
        t[ty + 8 * j][tx] = in[(long long)(r0 + ty + 8 * j) * C + c0 + tx];
    __syncthreads();
    #pragma unroll
    for (int j = 0; j < 4; j++) {
        float v = t[tx][ty + 8 * j];
        __half h, l; split_h(v, h, l);
        long long o = (long long)(c0 + ty + 8 * j) * R + r0 + tx;
        oh[o] = h; ol[o] = l;
    }
}

__global__ void transpose_split(const float* __restrict__ in,
                                __half* __restrict__ oh, __half* __restrict__ ol,
                                int R, int C)
{
    tsplit_body(in, oh, ol, R, C);
}

// Fused transpose-split of the four 1024x1024 weights (z = which weight).
__global__ void transpose_split_w4(const float* __restrict__ w0,
                                   const float* __restrict__ w1,
                                   const float* __restrict__ w2,
                                   const float* __restrict__ w3)
{
    const int z = blockIdx.z;
    const float* in = (z == 0) ? w0 : (z == 1) ? w1 : (z == 2) ? w2 : w3;
    tsplit_body(in, g_wth[0] + (long long)z * CH * CH - (z ? 0 : 0) + 0, // placeholder
                nullptr, CH, CH);
}

__global__ __launch_bounds__(256) void dwconv3(const float* __restrict__ cw)
{
    const int z = blockIdx.y;
    const float* X = (z == 0) ? g_q0 : (z == 1) ? g_k0 : g_v0;
    int idx = blockIdx.x * 256 + threadIdx.x;
    if (idx >= SEQ * CH) return;
    int c = idx & (CH - 1);
    int w = idx >> 10;
    float w0 = cw[c * 3 + 0], w1 = cw[c * 3 + 1], w2 = cw[c * 3 + 2];
    float acc = X[idx] * w1;
    if (w > 0)       acc += X[idx - CH] * w0;
    if (w < SEQ - 1) acc += X[idx + CH] * w2;
    if (z == 2) { g_vc[idx] = acc; return; }
    __half h, l; split_h(acc, h, l);
    if (z == 0) { g_qch[idx] = h; g_qcl[idx] = l; }
    else        { g_kch[idx] = h; g_kcl[idx] = l; }
}

// ---------------------------------------------------------------------------
// Softmax over half rows of g_Sh, in place.
// ---------------------------------------------------------------------------
__global__ __launch_bounds__(256) void softmax_rows()
{
    long long ro = ((long long)blockIdx.y * SEQ + blockIdx.x) * SEQ;
    uint4* row4 = (uint4*)(g_Sh + ro);
    const int tid = threadIdx.x;
    __shared__ float red[8];

    uint4 raw = row4[tid];
    __half2 hp[4] = { *(__half2*)&raw.x, *(__half2*)&raw.y,
                      *(__half2*)&raw.z, *(__half2*)&raw.w };
    float v[8];
    #pragma unroll
    for (int i = 0; i < 4; i++) {
        float2 f = __half22float2(hp[i]);
        v[2 * i] = f.x; v[2 * i + 1] = f.y;
    }

    float m = v[0];
    #pragma unroll
    for (int i = 1; i < 8; i++) m = fmaxf(m, v[i]);
    #pragma unroll
    for (int s = 16; s > 0; s >>= 1) m = fmaxf(m, __shfl_xor_sync(~0u, m, s));
    if ((tid & 31) == 0) red[tid >> 5] = m;
    __syncthreads();
    m = red[0];
    #pragma unroll
    for (int i = 1; i < 8; i++) m = fmaxf(m, red[i]);
    __syncthreads();

    float sum = 0.f;
    #pragma unroll
    for (int i = 0; i < 8; i++) { v[i] = __expf(v[i] - m); sum += v[i]; }
    #pragma unroll
    for (int s = 16; s > 0; s >>= 1) sum += __shfl_xor_sync(~0u, sum, s);
    if ((tid & 31) == 0) red[tid >> 5] = sum;
    __syncthreads();
    sum = 0.f;
    #pragma unroll
    for (int i = 0; i < 8; i++) sum += red[i];
    float inv = 1.0f / sum;

    uint4 outp;
    __half2* op = (__half2*)&outp;
    #pragma unroll
    for (int i = 0; i < 4; i++)
        op[i] = __floats2half2_rn(v[2 * i] * inv, v[2 * i + 1] * inv);
    row4[tid] = outp;
}

// ---------------------------------------------------------------------------
// Launch
// ---------------------------------------------------------------------------
extern "C" void kernel_launch(void* const* d_in, const int* in_sizes, int n_in,
                              void* d_out, int out_size)
{
    const float* x  = (const float*)d_in[0];
    const float* wq = (const float*)d_in[1];
    const float* wk = (const float*)d_in[2];
    const float* wv = (const float*)d_in[3];
    const float* wo = (const float*)d_in[4];
    const float* cw = (const float*)d_in[5];
    const float* er = (const float*)d_in[6];
    float* out = (float*)d_out;

    __half *wth, *wtl, *erth, *ertl, *vth, *vtl;
    float* vc;
    cudaGetSymbolAddress((void**)&wth,  g_wth);
    cudaGetSymbolAddress((void**)&wtl,  g_wtl);
    cudaGetSymbolAddress((void**)&erth, g_erth);
    cudaGetSymbolAddress((void**)&ertl, g_ertl);
    cudaGetSymbolAddress((void**)&vth,  g_vth);
    cudaGetSymbolAddress((void**)&vtl,  g_vtl);
    cudaGetSymbolAddress((void**)&vc,   g_vc);

    const int SMQKV = (1 * 128 * 48 + 2 * 128 * 48) * 3;            // 55,296
    const int SM128 = (2 * 128 * 48 + 2 * 128 * 48) * 3;            // 73,728
    const int SMAV  = (1 * 128 * 48 + 2 * 64 * 48) * 3;             // 36,864
    cudaFuncSetAttribute(qkv_pipe,   cudaFuncAttributeMaxDynamicSharedMemorySize, SMQKV);
    cudaFuncSetAttribute(wo_pipe,    cudaFuncAttributeMaxDynamicSharedMemorySize, SMQKV);
    cudaFuncSetAttribute(score_pipe, cudaFuncAttributeMaxDynamicSharedMemorySize, SM128);
    cudaFuncSetAttribute(av_pipe,    cudaFuncAttributeMaxDynamicSharedMemorySize, SMAV);

    dim3 blk(256);
    dim3 tblk(32, 8);

    // prep: x -> half; transpose-split weights + er
    split_x<<<SEQ * CH / 256, blk>>>(x);
    const float* ws[4] = {wq, wk, wv, wo};
    for (int z = 0; z < 4; z++)
        transpose_split<<<dim3(32, 32), tblk>>>(ws[z], wth + (long long)z * CH * CH,
                                                wtl + (long long)z * CH * CH, CH, CH);
    transpose_split<<<dim3(64, 2), tblk>>>(er, erth, ertl, HDIM, SEQ);

    // q/k/v projections (x2)
    qkv_pipe<<<dim3(CH / 128, SEQ / 128, 3), blk, SMQKV>>>();

    // depthwise conv (reference applies q_conv to q, k AND v)
    dwconv3<<<dim3(SEQ * CH / 256, 3), blk>>>(cw);
    transpose_split<<<dim3(32, 64), tblk>>>(vc, vth, vtl, SEQ, CH);

    // scores (x3, half out) + softmax (in place) + A@V (x2, half out)
    score_pipe<<<dim3(SEQ / 128, SEQ / 128, NHEAD), blk, SM128>>>();
    softmax_rows<<<dim3(SEQ, NHEAD), blk>>>();
    av_pipe<<<dim3(1, SEQ / 128, NHEAD), blk, SMAV>>>();

    // output projection (x2)
    wo_pipe<<<dim3(CH / 128, SEQ / 128, 1), blk, SMQKV>>>(out);
}

// round 13
// speedup vs baseline: 1.5036x; 1.1174x over previous
#include <cuda_runtime.h>
#include <cuda_fp16.h>
#include <cstdint>

constexpr int SEQ   = 2048;
constexpr int CH    = 1024;
constexpr int NHEAD = 16;
constexpr int HDIM  = 64;

// ---------------------------------------------------------------------------
// Scratch
// ---------------------------------------------------------------------------
__device__ __half g_xh[SEQ * CH];                            // x -> half, [w][c]
__device__ __half g_wth[4][CH * CH], g_wtl[4][CH * CH];      // W^T split, [n][k]
__device__ __half g_erth[SEQ * HDIM];                        // er^T hi, [i][d]
__device__ float  g_q0[SEQ * CH], g_k0[SEQ * CH], g_v0[SEQ * CH];
__device__ __half g_qch[SEQ * CH], g_qcl[SEQ * CH];          // conv(q) split, [w][c]
__device__ __half g_kch[SEQ * CH], g_kcl[SEQ * CH];
__device__ float  g_vc[SEQ * CH];                            // conv(v) fp32
__device__ __half g_vth[CH * SEQ], g_vtl[CH * SEQ];          // conv(v)^T split, [c][w]
__device__ __half g_Sh[(long long)NHEAD * SEQ * SEQ];        // half scores -> probs (in-place)
__device__ __half g_ath[SEQ * CH];                           // attn half, [w][c]

// ---------------------------------------------------------------------------
// Helpers
// ---------------------------------------------------------------------------
__device__ __forceinline__ uint32_t smem_u32(const void* p) {
    uint32_t a;
    asm("{ .reg .u64 t; cvta.to.shared.u64 t, %1; cvt.u32.u64 %0, t; }" : "=r"(a) : "l"(p));
    return a;
}
__device__ __forceinline__ void split_h(float x, __half& h, __half& l) {
    h = __float2half_rn(x);
    l = __float2half_rn(x - __half2float(h));
}
__device__ __forceinline__ void mma_f16(float* c, const uint32_t* a, const uint32_t* b) {
    asm volatile(
        "mma.sync.aligned.m16n8k16.row.col.f32.f16.f16.f32 "
        "{%0,%1,%2,%3},{%4,%5,%6,%7},{%8,%9},{%0,%1,%2,%3};"
        : "+f"(c[0]), "+f"(c[1]), "+f"(c[2]), "+f"(c[3])
        : "r"(a[0]), "r"(a[1]), "r"(a[2]), "r"(a[3]), "r"(b[0]), "r"(b[1]));
}
__device__ __forceinline__ void ldsm_x4(uint32_t* r, uint32_t addr) {
    asm volatile("ldmatrix.sync.aligned.m8n8.x4.shared.b16 {%0,%1,%2,%3}, [%4];"
        : "=r"(r[0]), "=r"(r[1]), "=r"(r[2]), "=r"(r[3]) : "r"(addr));
}
__device__ __forceinline__ void ldsm_x2(uint32_t* r, uint32_t addr) {
    asm volatile("ldmatrix.sync.aligned.m8n8.x2.shared.b16 {%0,%1}, [%2];"
        : "=r"(r[0]), "=r"(r[1]) : "r"(addr));
}
__device__ __forceinline__ void cpa16(uint32_t s, const void* g) {
    asm volatile("cp.async.ca.shared.global [%0], [%1], 16;" :: "r"(s), "l"(g));
}
#define CP_COMMIT() asm volatile("cp.async.commit_group;" ::: "memory")
#define CP_WAIT2()  asm volatile("cp.async.wait_group 2;" ::: "memory")

struct KtH { const __half* ah; const __half* al; const __half* bh; const __half* bl;
             int lda; int ldb; };

// ---------------------------------------------------------------------------
// 3-stage cp.async pipelined FP16 GEMM body (m16n8k16), ldmatrix fragments.
// ASPL: A hi/lo split (x3 MMAs) or single A (x2 MMAs: ah*bh + ah*bl).
// OMODE: 0 = fp32 C, 1 = split half Ch/Cl, 2 = half Ch only.
// ---------------------------------------------------------------------------
template<int BM, int BN, int WM, int WN, bool ASPL, int OMODE, typename F>
__device__ __forceinline__ void gemm_pipe(
    F&& ktf, int KT, float* C, __half* Ch, __half* Cl, int ldc, float alpha, char* sm_)
{
    constexpr int WARPS_M = BM / WM, WARPS_N = BN / WN;
    static_assert(WARPS_M * WARPS_N == 8, "");
    constexpr int MT = WM / 16, NT = WN / 8;
    constexpr int ABYT = BM * 48, BBYT = BN * 48;
    constexpr int NAARR = ASPL ? 2 : 1;
    constexpr int STB  = NAARR * ABYT + 2 * BBYT;
    constexpr int NSTG = 3;

    const uint32_t sb = smem_u32(sm_);
    const int tid = threadIdx.x, wid = tid >> 5, lane = tid & 31;
    const int gid = lane >> 2, tig = lane & 3;
    const int wm0 = (wid % WARPS_M) * WM, wn0 = (wid / WARPS_M) * WN;

    auto issue = [&](int s, int t) {
        KtH p = ktf(t);
        uint32_t st = sb + s * STB;
        #pragma unroll
        for (int i = 0; i < BM * 2 / 256; i++) {
            int id = tid + i * 256, row = id >> 1, c16 = id & 1;
            uint32_t sa = st + row * 48 + c16 * 16;
            cpa16(sa, p.ah + (long long)row * p.lda + c16 * 8);
            if (ASPL) cpa16(sa + ABYT, p.al + (long long)row * p.lda + c16 * 8);
        }
        #pragma unroll
        for (int i = 0; i < (BN * 2 + 255) / 256; i++) {
            int id = tid + i * 256;
            if (id < BN * 2) {
                int row = id >> 1, c16 = id & 1;
                uint32_t sa = st + NAARR * ABYT + row * 48 + c16 * 16;
                cpa16(sa,        p.bh + (long long)row * p.ldb + c16 * 8);
                cpa16(sa + BBYT, p.bl + (long long)row * p.ldb + c16 * 8);
            }
        }
    };

    float acc[MT][NT][4] = {};

    #pragma unroll
    for (int s = 0; s < NSTG; s++) {
        if (s < KT) issue(s, s);
        CP_COMMIT();
    }

    for (int t = 0; t < KT; t++) {
        int s = t % NSTG;
        CP_WAIT2();
        __syncthreads();

        uint32_t base = sb + s * STB;
        uint32_t ah[MT][4], al[MT][4], bh[NT][2], bl[NT][2];
        #pragma unroll
        for (int mt = 0; mt < MT; mt++) {
            uint32_t a0 = base + (wm0 + mt * 16 + (lane & 15)) * 48 + (lane >> 4) * 16;
            ldsm_x4(ah[mt], a0);
            if (ASPL) ldsm_x4(al[mt], a0 + ABYT);
        }
        #pragma unroll
        for (int nt = 0; nt < NT; nt++) {
            uint32_t b0 = base + NAARR * ABYT + (wn0 + nt * 8 + (lane & 7)) * 48
                        + ((lane >> 3) & 1) * 16;
            ldsm_x2(bh[nt], b0);
            ldsm_x2(bl[nt], b0 + BBYT);
        }
        #pragma unroll
        for (int mt = 0; mt < MT; mt++)
            #pragma unroll
            for (int nt = 0; nt < NT; nt++) {
                mma_f16(acc[mt][nt], ah[mt], bh[nt]);
                mma_f16(acc[mt][nt], ah[mt], bl[nt]);
                if (ASPL) mma_f16(acc[mt][nt], al[mt], bh[nt]);
            }
        __syncthreads();
        if (t + NSTG < KT) issue(s, t + NSTG);
        CP_COMMIT();
    }

    #pragma unroll
    for (int mt = 0; mt < MT; mt++)
        #pragma unroll
        for (int nt = 0; nt < NT; nt++) {
            int r = wm0 + mt * 16 + gid;
            int c = wn0 + nt * 8 + 2 * tig;
            #pragma unroll
            for (int half_ = 0; half_ < 2; half_++) {
                int rr = r + half_ * 8;
                float v0 = alpha * acc[mt][nt][half_ * 2 + 0];
                float v1 = alpha * acc[mt][nt][half_ * 2 + 1];
                if (OMODE == 1) {
                    __half h0, l0, h1, l1;
                    split_h(v0, h0, l0); split_h(v1, h1, l1);
                    *(__half2*)(Ch + (long long)rr * ldc + c) = __halves2half2(h0, h1);
                    *(__half2*)(Cl + (long long)rr * ldc + c) = __halves2half2(l0, l1);
                } else if (OMODE == 2) {
                    *(__half2*)(Ch + (long long)rr * ldc + c) = __floats2half2_rn(v0, v1);
                } else {
                    *(float2*)(C + (long long)rr * ldc + c) = make_float2(v0, v1);
                }
            }
        }
}

// ---------------------------------------------------------------------------
// GEMM kernels
// ---------------------------------------------------------------------------
// q/k/v projections: A = x (half, single), B = W^T split  -> x2 MMAs
__global__ __launch_bounds__(256, 2) void qkv_pipe()
{
    extern __shared__ char smem[];
    const int z = blockIdx.z;
    const int m0 = blockIdx.y * 128, n0 = blockIdx.x * 128;
    float* O = ((z == 0) ? g_q0 : (z == 1) ? g_k0 : g_v0) + (long long)m0 * CH + n0;
    const __half* Ah = g_xh + (long long)m0 * CH;
    const __half* Bh = g_wth[z] + (long long)n0 * CH;
    const __half* Bl = g_wtl[z] + (long long)n0 * CH;
    auto ktf = [&](int t) -> KtH {
        return { Ah + t * 16, Ah + t * 16, Bh + t * 16, Bl + t * 16, CH, CH };
    };
    gemm_pipe<128, 128, 64, 32, false, 0>(ktf, CH / 16, O, nullptr, nullptr, CH, 1.f, smem);
}

// output projection: A = attn (half, single), B = wo^T split -> x2 MMAs
__global__ __launch_bounds__(256, 2) void wo_pipe(float* __restrict__ out)
{
    extern __shared__ char smem[];
    const int m0 = blockIdx.y * 128, n0 = blockIdx.x * 128;
    const __half* Ah = g_ath + (long long)m0 * CH;
    const __half* Bh = g_wth[3] + (long long)n0 * CH;
    const __half* Bl = g_wtl[3] + (long long)n0 * CH;
    float* O = out + (long long)m0 * CH + n0;
    auto ktf = [&](int t) -> KtH {
        return { Ah + t * 16, Ah + t * 16, Bh + t * 16, Bl + t * 16, CH, CH };
    };
    gemm_pipe<128, 128, 64, 32, false, 0>(ktf, CH / 16, O, nullptr, nullptr, CH, 1.f, smem);
}

// Score: S[h,i,j] = ( q_i.k_j + erT_i.q_j ) / 32 — virtual K = 128, x2
// (A = q-hi / erT-hi only; B keeps hi+lo; fp16 S storage already bounds
//  logit precision at the same 2^-11 level the dropped term corrects).
__global__ __launch_bounds__(256, 2) void score_pipe()
{
    extern __shared__ char smem[];
    const int h = blockIdx.z, cb = h * HDIM;
    const int i0 = blockIdx.y * 128, j0 = blockIdx.x * 128;
    __half* O = g_Sh + ((long long)h * SEQ + i0) * SEQ + j0;
    auto ktf = [&](int t) -> KtH {
        if (t < 4) {
            const __half* a = g_qch + (long long)i0 * CH + cb + t * 16;
            return { a, a,
                     g_kch + (long long)j0 * CH + cb + t * 16,
                     g_kcl + (long long)j0 * CH + cb + t * 16, CH, CH };
        }
        int d0 = (t - 4) * 16;
        const __half* a = g_erth + (long long)i0 * HDIM + d0;
        return { a, a,
                 g_qch + (long long)j0 * CH + cb + d0,
                 g_qcl + (long long)j0 * CH + cb + d0, HDIM, CH };
    };
    gemm_pipe<128, 128, 64, 32, false, 2>(ktf, 8, nullptr, O, nullptr, SEQ, 0.03125f, smem);
}

// A @ V per head: A = probs (half single), B = V^T split. Half output (g_ath only).
__global__ __launch_bounds__(256, 2) void av_pipe()
{
    extern __shared__ char smem[];
    const int h = blockIdx.z;
    const int m0 = blockIdx.y * 128;
    const __half* Ah = g_Sh + ((long long)h * SEQ + m0) * SEQ;
    const __half* Bh = g_vth + (long long)(h * HDIM) * SEQ;
    const __half* Bl = g_vtl + (long long)(h * HDIM) * SEQ;
    __half* Oh = g_ath + (long long)m0 * CH + h * HDIM;
    auto ktf = [&](int t) -> KtH {
        return { Ah + t * 16, Ah + t * 16, Bh + t * 16, Bl + t * 16, SEQ, SEQ };
    };
    gemm_pipe<128, 64, 32, 32, false, 2>(ktf, SEQ / 16, nullptr, Oh, nullptr, CH, 1.f, smem);
}

// ---------------------------------------------------------------------------
// Prep kernels
// ---------------------------------------------------------------------------
__global__ __launch_bounds__(256) void split_x(const float* __restrict__ x)
{
    int i = blockIdx.x * 256 + threadIdx.x;
    if (i >= SEQ * CH) return;
    g_xh[i] = __float2half_rn(x[i]);
}

// in[R][C] fp32 -> out[C][R] split halves (tiled, coalesced both sides)
__device__ __forceinline__ void tsplit_body(
    const float* __restrict__ in, __half* __restrict__ oh, __half* __restrict__ ol,
    int R, int C)
{
    __shared__ float t[32][33];
    int c0 = blockIdx.x * 32, r0 = blockIdx.y * 32;
    int tx = threadIdx.x, ty = threadIdx.y;   // 32 x 8
    #pragma unroll
    for (int j = 0; j < 4; j++)
        t[ty + 8 * j][tx] = in[(long long)(r0 + ty + 8 * j) * C + c0 + tx];
    __syncthreads();
    #pragma unroll
    for (int j = 0; j < 4; j++) {
        float v = t[tx][ty + 8 * j];
        __half h, l; split_h(v, h, l);
        long long o = (long long)(c0 + ty + 8 * j) * R + r0 + tx;
        oh[o] = h;
        if (ol) ol[o] = l;
    }
}

__global__ void transpose_split(const float* __restrict__ in,
                                __half* __restrict__ oh, __half* __restrict__ ol,
                                int R, int C)
{
    tsplit_body(in, oh, ol, R, C);
}

// Fused transpose-split of the four 1024x1024 weights (grid.z = which weight).
__global__ void transpose_split_w4(const float* __restrict__ w0,
                                   const float* __restrict__ w1,
                                   const float* __restrict__ w2,
                                   const float* __restrict__ w3)
{
    const int z = blockIdx.z;
    const float* in = (z == 0) ? w0 : (z == 1) ? w1 : (z == 2) ? w2 : w3;
    tsplit_body(in, g_wth[z], g_wtl[z], CH, CH);
}

__global__ __launch_bounds__(256) void dwconv3(const float* __restrict__ cw)
{
    const int z = blockIdx.y;
    const float* X = (z == 0) ? g_q0 : (z == 1) ? g_k0 : g_v0;
    int idx = blockIdx.x * 256 + threadIdx.x;
    if (idx >= SEQ * CH) return;
    int c = idx & (CH - 1);
    int w = idx >> 10;
    float w0 = cw[c * 3 + 0], w1 = cw[c * 3 + 1], w2 = cw[c * 3 + 2];
    float acc = X[idx] * w1;
    if (w > 0)       acc += X[idx - CH] * w0;
    if (w < SEQ - 1) acc += X[idx + CH] * w2;
    if (z == 2) { g_vc[idx] = acc; return; }
    __half h, l; split_h(acc, h, l);
    if (z == 0) { g_qch[idx] = h; g_qcl[idx] = l; }
    else        { g_kch[idx] = h; g_kcl[idx] = l; }
}

// ---------------------------------------------------------------------------
// Softmax over half rows of g_Sh, in place.
// ---------------------------------------------------------------------------
__global__ __launch_bounds__(256) void softmax_rows()
{
    long long ro = ((long long)blockIdx.y * SEQ + blockIdx.x) * SEQ;
    uint4* row4 = (uint4*)(g_Sh + ro);
    const int tid = threadIdx.x;
    __shared__ float red[8];

    uint4 raw = row4[tid];
    __half2 hp[4] = { *(__half2*)&raw.x, *(__half2*)&raw.y,
                      *(__half2*)&raw.z, *(__half2*)&raw.w };
    float v[8];
    #pragma unroll
    for (int i = 0; i < 4; i++) {
        float2 f = __half22float2(hp[i]);
        v[2 * i] = f.x; v[2 * i + 1] = f.y;
    }

    float m = v[0];
    #pragma unroll
    for (int i = 1; i < 8; i++) m = fmaxf(m, v[i]);
    #pragma unroll
    for (int s = 16; s > 0; s >>= 1) m = fmaxf(m, __shfl_xor_sync(~0u, m, s));
    if ((tid & 31) == 0) red[tid >> 5] = m;
    __syncthreads();
    m = red[0];
    #pragma unroll
    for (int i = 1; i < 8; i++) m = fmaxf(m, red[i]);
    __syncthreads();

    float sum = 0.f;
    #pragma unroll
    for (int i = 0; i < 8; i++) { v[i] = __expf(v[i] - m); sum += v[i]; }
    #pragma unroll
    for (int s = 16; s > 0; s >>= 1) sum += __shfl_xor_sync(~0u, sum, s);
    if ((tid & 31) == 0) red[tid >> 5] = sum;
    __syncthreads();
    sum = 0.f;
    #pragma unroll
    for (int i = 0; i < 8; i++) sum += red[i];
    float inv = 1.0f / sum;

    uint4 outp;
    __half2* op = (__half2*)&outp;
    #pragma unroll
    for (int i = 0; i < 4; i++)
        op[i] = __floats2half2_rn(v[2 * i] * inv, v[2 * i + 1] * inv);
    row4[tid] = outp;
}

// ---------------------------------------------------------------------------
// Launch
// ---------------------------------------------------------------------------
extern "C" void kernel_launch(void* const* d_in, const int* in_sizes, int n_in,
                              void* d_out, int out_size)
{
    const float* x  = (const float*)d_in[0];
    const float* wq = (const float*)d_in[1];
    const float* wk = (const float*)d_in[2];
    const float* wv = (const float*)d_in[3];
    const float* wo = (const float*)d_in[4];
    const float* cw = (const float*)d_in[5];
    const float* er = (const float*)d_in[6];
    float* out = (float*)d_out;

    __half *erth, *vth, *vtl;
    float* vc;
    cudaGetSymbolAddress((void**)&erth, g_erth);
    cudaGetSymbolAddress((void**)&vth,  g_vth);
    cudaGetSymbolAddress((void**)&vtl,  g_vtl);
    cudaGetSymbolAddress((void**)&vc,   g_vc);

    const int SMX2  = (1 * 128 * 48 + 2 * 128 * 48) * 3;            // 55,296
    const int SMAV  = (1 * 128 * 48 + 2 * 64 * 48) * 3;             // 36,864
    cudaFuncSetAttribute(qkv_pipe,   cudaFuncAttributeMaxDynamicSharedMemorySize, SMX2);
    cudaFuncSetAttribute(wo_pipe,    cudaFuncAttributeMaxDynamicSharedMemorySize, SMX2);
    cudaFuncSetAttribute(score_pipe, cudaFuncAttributeMaxDynamicSharedMemorySize, SMX2);
    cudaFuncSetAttribute(av_pipe,    cudaFuncAttributeMaxDynamicSharedMemorySize, SMAV);

    dim3 blk(256);
    dim3 tblk(32, 8);

    // prep: x -> half; fused transpose-split of all four weights; er^T hi only
    split_x<<<SEQ * CH / 256, blk>>>(x);
    transpose_split_w4<<<dim3(32, 32, 4), tblk>>>(wq, wk, wv, wo);
    transpose_split<<<dim3(64, 2), tblk>>>(er, erth, nullptr, HDIM, SEQ);

    // q/k/v projections (x2)
    qkv_pipe<<<dim3(CH / 128, SEQ / 128, 3), blk, SMX2>>>();

    // depthwise conv (reference applies q_conv to q, k AND v)
    dwconv3<<<dim3(SEQ * CH / 256, 3), blk>>>(cw);
    transpose_split<<<dim3(32, 64), tblk>>>(vc, vth, vtl, SEQ, CH);

    // scores (x2, half out) + softmax (in place) + A@V (x2, half out)
    score_pipe<<<dim3(SEQ / 128, SEQ / 128, NHEAD), blk, SMX2>>>();
    softmax_rows<<<dim3(SEQ, NHEAD), blk>>>();
    av_pipe<<<dim3(1, SEQ / 128, NHEAD), blk, SMAV>>>();

    // output projection (x2)
    wo_pipe<<<dim3(CH / 128, SEQ / 128, 1), blk, SMX2>>>(out);
}

// round 14
// speedup vs baseline: 1.8042x; 1.1999x over previous
#include <cuda_runtime.h>
#include <cuda_fp16.h>
#include <cstdint>

constexpr int SEQ   = 2048;
constexpr int CH    = 1024;
constexpr int NHEAD = 16;
constexpr int HDIM  = 64;

// ---------------------------------------------------------------------------
// Scratch
// ---------------------------------------------------------------------------
__device__ __half g_xh[SEQ * CH];                            // x -> half, [w][c]
__device__ __half g_wth[4][CH * CH], g_wtl[4][CH * CH];      // W^T split, [n][k]
__device__ __half g_erth[SEQ * HDIM];                        // er^T hi, [i][d]
__device__ float  g_q0[SEQ * CH], g_k0[SEQ * CH], g_v0[SEQ * CH];
__device__ __half g_qch[SEQ * CH], g_qcl[SEQ * CH];          // conv(q) split, [w][c]
__device__ __half g_kch[SEQ * CH], g_kcl[SEQ * CH];
__device__ float  g_vc[SEQ * CH];                            // conv(v) fp32
__device__ __half g_vth[CH * SEQ], g_vtl[CH * SEQ];          // conv(v)^T split, [c][w]
__device__ __half g_Sh[(long long)NHEAD * SEQ * SEQ];        // half scores -> probs (in-place)
__device__ __half g_ath[SEQ * CH];                           // attn half, [w][c]

// ---------------------------------------------------------------------------
// Helpers
// ---------------------------------------------------------------------------
__device__ __forceinline__ uint32_t smem_u32(const void* p) {
    uint32_t a;
    asm("{ .reg .u64 t; cvta.to.shared.u64 t, %1; cvt.u32.u64 %0, t; }" : "=r"(a) : "l"(p));
    return a;
}
__device__ __forceinline__ void split_h(float x, __half& h, __half& l) {
    h = __float2half_rn(x);
    l = __float2half_rn(x - __half2float(h));
}
__device__ __forceinline__ void mma_f16(float* c, const uint32_t* a, const uint32_t* b) {
    asm volatile(
        "mma.sync.aligned.m16n8k16.row.col.f32.f16.f16.f32 "
        "{%0,%1,%2,%3},{%4,%5,%6,%7},{%8,%9},{%0,%1,%2,%3};"
        : "+f"(c[0]), "+f"(c[1]), "+f"(c[2]), "+f"(c[3])
        : "r"(a[0]), "r"(a[1]), "r"(a[2]), "r"(a[3]), "r"(b[0]), "r"(b[1]));
}
__device__ __forceinline__ void ldsm_x4(uint32_t* r, uint32_t addr) {
    asm volatile("ldmatrix.sync.aligned.m8n8.x4.shared.b16 {%0,%1,%2,%3}, [%4];"
        : "=r"(r[0]), "=r"(r[1]), "=r"(r[2]), "=r"(r[3]) : "r"(addr));
}
__device__ __forceinline__ void ldsm_x2(uint32_t* r, uint32_t addr) {
    asm volatile("ldmatrix.sync.aligned.m8n8.x2.shared.b16 {%0,%1}, [%2];"
        : "=r"(r[0]), "=r"(r[1]) : "r"(addr));
}
__device__ __forceinline__ void cpa16(uint32_t s, const void* g) {
    asm volatile("cp.async.ca.shared.global [%0], [%1], 16;" :: "r"(s), "l"(g));
}
#define CP_COMMIT() asm volatile("cp.async.commit_group;" ::: "memory")
#define CP_WAIT2()  asm volatile("cp.async.wait_group 2;" ::: "memory")

struct KtH { const __half* ah; const __half* al; const __half* bh; const __half* bl;
             int lda; int ldb; };

// ---------------------------------------------------------------------------
// 3-stage cp.async pipelined FP16 GEMM body, k-tile = 32 (two 16-k chunks per
// stage -> half the barrier/wait density). Row stride 80 B (conflict-free for
// both cp.async stores and ldmatrix reads).
// ASPL: A hi/lo split (x3 MMAs) or single A (x2 MMAs: ah*bh + ah*bl).
// OMODE: 0 = fp32 C, 1 = split half Ch/Cl, 2 = half Ch only.
// ---------------------------------------------------------------------------
template<int BM, int BN, int WM, int WN, bool ASPL, int OMODE, typename F>
__device__ __forceinline__ void gemm_pipe(
    F&& ktf, int KT, float* C, __half* Ch, __half* Cl, int ldc, float alpha, char* sm_)
{
    constexpr int WARPS_M = BM / WM, WARPS_N = BN / WN;
    static_assert(WARPS_M * WARPS_N == 8, "");
    constexpr int MT = WM / 16, NT = WN / 8;
    constexpr int ROWB = 80;                        // 32 halfs + 16B pad
    constexpr int ABYT = BM * ROWB, BBYT = BN * ROWB;
    constexpr int NAARR = ASPL ? 2 : 1;
    constexpr int STB  = NAARR * ABYT + 2 * BBYT;
    constexpr int NSTG = 3;

    const uint32_t sb = smem_u32(sm_);
    const int tid = threadIdx.x, wid = tid >> 5, lane = tid & 31;
    const int gid = lane >> 2, tig = lane & 3;
    const int wm0 = (wid % WARPS_M) * WM, wn0 = (wid / WARPS_M) * WN;

    auto issue = [&](int s, int t) {
        KtH p = ktf(t);
        uint32_t st = sb + s * STB;
        #pragma unroll
        for (int i = 0; i < BM * 4 / 256; i++) {
            int id = tid + i * 256, row = id >> 2, c16 = id & 3;
            uint32_t sa = st + row * ROWB + c16 * 16;
            cpa16(sa, p.ah + (long long)row * p.lda + c16 * 8);
            if (ASPL) cpa16(sa + ABYT, p.al + (long long)row * p.lda + c16 * 8);
        }
        #pragma unroll
        for (int i = 0; i < (BN * 4 + 255) / 256; i++) {
            int id = tid + i * 256;
            if (id < BN * 4) {
                int row = id >> 2, c16 = id & 3;
                uint32_t sa = st + NAARR * ABYT + row * ROWB + c16 * 16;
                cpa16(sa,        p.bh + (long long)row * p.ldb + c16 * 8);
                cpa16(sa + BBYT, p.bl + (long long)row * p.ldb + c16 * 8);
            }
        }
    };

    float acc[MT][NT][4] = {};

    #pragma unroll
    for (int s = 0; s < NSTG; s++) {
        if (s < KT) issue(s, s);
        CP_COMMIT();
    }

    for (int t = 0; t < KT; t++) {
        int s = t % NSTG;
        CP_WAIT2();
        __syncthreads();

        uint32_t base = sb + s * STB;
        #pragma unroll
        for (int ck = 0; ck < 2; ck++) {            // two 16-k chunks per stage
            uint32_t co = (uint32_t)ck * 32;
            uint32_t ah[MT][4], al[MT][4], bh[NT][2], bl[NT][2];
            #pragma unroll
            for (int mt = 0; mt < MT; mt++) {
                uint32_t a0 = base + (wm0 + mt * 16 + (lane & 15)) * ROWB + co
                            + (lane >> 4) * 16;
                ldsm_x4(ah[mt], a0);
                if (ASPL) ldsm_x4(al[mt], a0 + ABYT);
            }
            #pragma unroll
            for (int nt = 0; nt < NT; nt++) {
                uint32_t b0 = base + NAARR * ABYT + (wn0 + nt * 8 + (lane & 7)) * ROWB
                            + co + ((lane >> 3) & 1) * 16;
                ldsm_x2(bh[nt], b0);
                ldsm_x2(bl[nt], b0 + BBYT);
            }
            #pragma unroll
            for (int mt = 0; mt < MT; mt++)
                #pragma unroll
                for (int nt = 0; nt < NT; nt++) {
                    mma_f16(acc[mt][nt], ah[mt], bh[nt]);
                    mma_f16(acc[mt][nt], ah[mt], bl[nt]);
                    if (ASPL) mma_f16(acc[mt][nt], al[mt], bh[nt]);
                }
        }
        __syncthreads();
        if (t + NSTG < KT) issue(s, t + NSTG);
        CP_COMMIT();
    }

    #pragma unroll
    for (int mt = 0; mt < MT; mt++)
        #pragma unroll
        for (int nt = 0; nt < NT; nt++) {
            int r = wm0 + mt * 16 + gid;
            int c = wn0 + nt * 8 + 2 * tig;
            #pragma unroll
            for (int half_ = 0; half_ < 2; half_++) {
                int rr = r + half_ * 8;
                float v0 = alpha * acc[mt][nt][half_ * 2 + 0];
                float v1 = alpha * acc[mt][nt][half_ * 2 + 1];
                if (OMODE == 1) {
                    __half h0, l0, h1, l1;
                    split_h(v0, h0, l0); split_h(v1, h1, l1);
                    *(__half2*)(Ch + (long long)rr * ldc + c) = __halves2half2(h0, h1);
                    *(__half2*)(Cl + (long long)rr * ldc + c) = __halves2half2(l0, l1);
                } else if (OMODE == 2) {
                    *(__half2*)(Ch + (long long)rr * ldc + c) = __floats2half2_rn(v0, v1);
                } else {
                    *(float2*)(C + (long long)rr * ldc + c) = make_float2(v0, v1);
                }
            }
        }
}

// ---------------------------------------------------------------------------
// GEMM kernels (k-tile = 32 now)
// ---------------------------------------------------------------------------
// q/k/v projections: A = x (half, single), B = W^T split  -> x2 MMAs
__global__ __launch_bounds__(256, 2) void qkv_pipe()
{
    extern __shared__ char smem[];
    const int z = blockIdx.z;
    const int m0 = blockIdx.y * 128, n0 = blockIdx.x * 128;
    float* O = ((z == 0) ? g_q0 : (z == 1) ? g_k0 : g_v0) + (long long)m0 * CH + n0;
    const __half* Ah = g_xh + (long long)m0 * CH;
    const __half* Bh = g_wth[z] + (long long)n0 * CH;
    const __half* Bl = g_wtl[z] + (long long)n0 * CH;
    auto ktf = [&](int t) -> KtH {
        return { Ah + t * 32, Ah + t * 32, Bh + t * 32, Bl + t * 32, CH, CH };
    };
    gemm_pipe<128, 128, 64, 32, false, 0>(ktf, CH / 32, O, nullptr, nullptr, CH, 1.f, smem);
}

// output projection: A = attn (half, single), B = wo^T split -> x2 MMAs
__global__ __launch_bounds__(256, 2) void wo_pipe(float* __restrict__ out)
{
    extern __shared__ char smem[];
    const int m0 = blockIdx.y * 128, n0 = blockIdx.x * 128;
    const __half* Ah = g_ath + (long long)m0 * CH;
    const __half* Bh = g_wth[3] + (long long)n0 * CH;
    const __half* Bl = g_wtl[3] + (long long)n0 * CH;
    float* O = out + (long long)m0 * CH + n0;
    auto ktf = [&](int t) -> KtH {
        return { Ah + t * 32, Ah + t * 32, Bh + t * 32, Bl + t * 32, CH, CH };
    };
    gemm_pipe<128, 128, 64, 32, false, 0>(ktf, CH / 32, O, nullptr, nullptr, CH, 1.f, smem);
}

// Score: S[h,i,j] = ( q_i.k_j + erT_i.q_j ) / 32 — virtual K = 128 (4 x 32), x2
__global__ __launch_bounds__(256, 2) void score_pipe()
{
    extern __shared__ char smem[];
    const int h = blockIdx.z, cb = h * HDIM;
    const int i0 = blockIdx.y * 128, j0 = blockIdx.x * 128;
    __half* O = g_Sh + ((long long)h * SEQ + i0) * SEQ + j0;
    auto ktf = [&](int t) -> KtH {
        if (t < 2) {
            const __half* a = g_qch + (long long)i0 * CH + cb + t * 32;
            return { a, a,
                     g_kch + (long long)j0 * CH + cb + t * 32,
                     g_kcl + (long long)j0 * CH + cb + t * 32, CH, CH };
        }
        int d0 = (t - 2) * 32;
        const __half* a = g_erth + (long long)i0 * HDIM + d0;
        return { a, a,
                 g_qch + (long long)j0 * CH + cb + d0,
                 g_qcl + (long long)j0 * CH + cb + d0, HDIM, CH };
    };
    gemm_pipe<128, 128, 64, 32, false, 2>(ktf, 4, nullptr, O, nullptr, SEQ, 0.03125f, smem);
}

// A @ V per head: A = probs (half single), B = V^T split. Half output.
__global__ __launch_bounds__(256, 2) void av_pipe()
{
    extern __shared__ char smem[];
    const int h = blockIdx.z;
    const int m0 = blockIdx.y * 128;
    const __half* Ah = g_Sh + ((long long)h * SEQ + m0) * SEQ;
    const __half* Bh = g_vth + (long long)(h * HDIM) * SEQ;
    const __half* Bl = g_vtl + (long long)(h * HDIM) * SEQ;
    __half* Oh = g_ath + (long long)m0 * CH + h * HDIM;
    auto ktf = [&](int t) -> KtH {
        return { Ah + t * 32, Ah + t * 32, Bh + t * 32, Bl + t * 32, SEQ, SEQ };
    };
    gemm_pipe<128, 64, 32, 32, false, 2>(ktf, SEQ / 32, nullptr, Oh, nullptr, CH, 1.f, smem);
}

// ---------------------------------------------------------------------------
// Prep kernels
// ---------------------------------------------------------------------------
__global__ __launch_bounds__(256) void split_x(const float* __restrict__ x)
{
    int i = blockIdx.x * 256 + threadIdx.x;
    if (i >= SEQ * CH) return;
    g_xh[i] = __float2half_rn(x[i]);
}

// in[R][C] fp32 -> out[C][R] split halves (tiled, coalesced both sides)
__device__ __forceinline__ void tsplit_body(
    const float* __restrict__ in, __half* __restrict__ oh, __half* __restrict__ ol,
    int R, int C)
{
    __shared__ float t[32][33];
    int c0 = blockIdx.x * 32, r0 = blockIdx.y * 32;
    int tx = threadIdx.x, ty = threadIdx.y;   // 32 x 8
    #pragma unroll
    for (int j = 0; j < 4; j++)
        t[ty + 8 * j][tx] = in[(long long)(r0 + ty + 8 * j) * C + c0 + tx];
    __syncthreads();
    #pragma unroll
    for (int j = 0; j < 4; j++) {
        float v = t[tx][ty + 8 * j];
        __half h, l; split_h(v, h, l);
        long long o = (long long)(c0 + ty + 8 * j) * R + r0 + tx;
        oh[o] = h;
        if (ol) ol[o] = l;
    }
}

__global__ void transpose_split(const float* __restrict__ in,
                                __half* __restrict__ oh, __half* __restrict__ ol,
                                int R, int C)
{
    tsplit_body(in, oh, ol, R, C);
}

// Fused transpose-split of the four 1024x1024 weights (grid.z = which weight).
__global__ void transpose_split_w4(const float* __restrict__ w0,
                                   const float* __restrict__ w1,
                                   const float* __restrict__ w2,
                                   const float* __restrict__ w3)
{
    const int z = blockIdx.z;
    const float* in = (z == 0) ? w0 : (z == 1) ? w1 : (z == 2) ? w2 : w3;
    tsplit_body(in, g_wth[z], g_wtl[z], CH, CH);
}

__global__ __launch_bounds__(256) void dwconv3(const float* __restrict__ cw)
{
    const int z = blockIdx.y;
    const float* X = (z == 0) ? g_q0 : (z == 1) ? g_k0 : g_v0;
    int idx = blockIdx.x * 256 + threadIdx.x;
    if (idx >= SEQ * CH) return;
    int c = idx & (CH - 1);
    int w = idx >> 10;
    float w0 = cw[c * 3 + 0], w1 = cw[c * 3 + 1], w2 = cw[c * 3 + 2];
    float acc = X[idx] * w1;
    if (w > 0)       acc += X[idx - CH] * w0;
    if (w < SEQ - 1) acc += X[idx + CH] * w2;
    if (z == 2) { g_vc[idx] = acc; return; }
    __half h, l; split_h(acc, h, l);
    if (z == 0) { g_qch[idx] = h; g_qcl[idx] = l; }
    else        { g_kch[idx] = h; g_kcl[idx] = l; }
}

// ---------------------------------------------------------------------------
// Softmax over half rows of g_Sh, in place.
// ---------------------------------------------------------------------------
__global__ __launch_bounds__(256) void softmax_rows()
{
    long long ro = ((long long)blockIdx.y * SEQ + blockIdx.x) * SEQ;
    uint4* row4 = (uint4*)(g_Sh + ro);
    const int tid = threadIdx.x;
    __shared__ float red[8];

    uint4 raw = row4[tid];
    __half2 hp[4] = { *(__half2*)&raw.x, *(__half2*)&raw.y,
                      *(__half2*)&raw.z, *(__half2*)&raw.w };
    float v[8];
    #pragma unroll
    for (int i = 0; i < 4; i++) {
        float2 f = __half22float2(hp[i]);
        v[2 * i] = f.x; v[2 * i + 1] = f.y;
    }

    float m = v[0];
    #pragma unroll
    for (int i = 1; i < 8; i++) m = fmaxf(m, v[i]);
    #pragma unroll
    for (int s = 16; s > 0; s >>= 1) m = fmaxf(m, __shfl_xor_sync(~0u, m, s));
    if ((tid & 31) == 0) red[tid >> 5] = m;
    __syncthreads();
    m = red[0];
    #pragma unroll
    for (int i = 1; i < 8; i++) m = fmaxf(m, red[i]);
    __syncthreads();

    float sum = 0.f;
    #pragma unroll
    for (int i = 0; i < 8; i++) { v[i] = __expf(v[i] - m); sum += v[i]; }
    #pragma unroll
    for (int s = 16; s > 0; s >>= 1) sum += __shfl_xor_sync(~0u, sum, s);
    if ((tid & 31) == 0) red[tid >> 5] = sum;
    __syncthreads();
    sum = 0.f;
    #pragma unroll
    for (int i = 0; i < 8; i++) sum += red[i];
    float inv = 1.0f / sum;

    uint4 outp;
    __half2* op = (__half2*)&outp;
    #pragma unroll
    for (int i = 0; i < 4; i++)
        op[i] = __floats2half2_rn(v[2 * i] * inv, v[2 * i + 1] * inv);
    row4[tid] = outp;
}

// ---------------------------------------------------------------------------
// Launch
// ---------------------------------------------------------------------------
extern "C" void kernel_launch(void* const* d_in, const int* in_sizes, int n_in,
                              void* d_out, int out_size)
{
    const float* x  = (const float*)d_in[0];
    const float* wq = (const float*)d_in[1];
    const float* wk = (const float*)d_in[2];
    const float* wv = (const float*)d_in[3];
    const float* wo = (const float*)d_in[4];
    const float* cw = (const float*)d_in[5];
    const float* er = (const float*)d_in[6];
    float* out = (float*)d_out;

    __half *erth, *vth, *vtl;
    float* vc;
    cudaGetSymbolAddress((void**)&erth, g_erth);
    cudaGetSymbolAddress((void**)&vth,  g_vth);
    cudaGetSymbolAddress((void**)&vtl,  g_vtl);
    cudaGetSymbolAddress((void**)&vc,   g_vc);

    const int SMX2 = (1 * 128 + 2 * 128) * 80 * 3;   // 92,160
    const int SMAV = (1 * 128 + 2 * 64) * 80 * 3;    // 61,440
    cudaFuncSetAttribute(qkv_pipe,   cudaFuncAttributeMaxDynamicSharedMemorySize, SMX2);
    cudaFuncSetAttribute(wo_pipe,    cudaFuncAttributeMaxDynamicSharedMemorySize, SMX2);
    cudaFuncSetAttribute(score_pipe, cudaFuncAttributeMaxDynamicSharedMemorySize, SMX2);
    cudaFuncSetAttribute(av_pipe,    cudaFuncAttributeMaxDynamicSharedMemorySize, SMAV);

    dim3 blk(256);
    dim3 tblk(32, 8);

    // prep: x -> half; fused transpose-split of all four weights; er^T hi only
    split_x<<<SEQ * CH / 256, blk>>>(x);
    transpose_split_w4<<<dim3(32, 32, 4), tblk>>>(wq, wk, wv, wo);
    transpose_split<<<dim3(64, 2), tblk>>>(er, erth, nullptr, HDIM, SEQ);

    // q/k/v projections (x2)
    qkv_pipe<<<dim3(CH / 128, SEQ / 128, 3), blk, SMX2>>>();

    // depthwise conv (reference applies q_conv to q, k AND v)
    dwconv3<<<dim3(SEQ * CH / 256, 3), blk>>>(cw);
    transpose_split<<<dim3(32, 64), tblk>>>(vc, vth, vtl, SEQ, CH);

    // scores (x2, half out) + softmax (in place) + A@V (x2, half out)
    score_pipe<<<dim3(SEQ / 128, SEQ / 128, NHEAD), blk, SMX2>>>();
    softmax_rows<<<dim3(SEQ, NHEAD), blk>>>();
    av_pipe<<<dim3(1, SEQ / 128, NHEAD), blk, SMAV>>>();

    // output projection (x2)
    wo_pipe<<<dim3(CH / 128, SEQ / 128, 1), blk, SMX2>>>(out);
}